// round 5
// baseline (speedup 1.0000x reference)
#include <cuda_runtime.h>
#include <cuda_bf16.h>
#include <math.h>
#include <stdint.h>

#define BB 8
#define SS 4096
#define DD 1024
#define FF 512
#define M_TOTAL (BB*SS)   // 32768
#define MAXP 8
#define NKT 32            // 1024/32 k-tiles
#define BK 32

// ---------------- device scratch ----------------
// X as bf16, tile-linear: [mtile 0..255][kt 0..31][row 0..127][64 B]
__device__ uint2 g_Xb[(size_t)M_TOTAL * (DD/4)];         // 64 MB  (256 uint2 per row)
// W1 as bf16, tile-linear: [kt 0..31][n 0..511][64 B]
__device__ uint32_t g_Bpk[NKT * FF * (BK/2)];            // 1 MB
__device__ float g_partial[M_TOTAL*8];
__device__ float g_scores[M_TOTAL];
__device__ float g_norm2[M_TOTAL];
__device__ float g_dot[M_TOTAL];
__device__ float g_pooled[BB*MAXP*DD];
__device__ int g_first, g_last;

// ---------------- helpers ----------------
__device__ __forceinline__ uint32_t s2u(const void* p){
    uint32_t a;
    asm("{ .reg .u64 t; cvta.to.shared.u64 t, %1; cvt.u32.u64 %0, t; }" : "=r"(a) : "l"(p));
    return a;
}
__device__ __forceinline__ void cp16(uint32_t dst, const void* src){
    asm volatile("cp.async.cg.shared.global [%0], [%1], 16;" :: "r"(dst), "l"(src) : "memory");
}
__device__ __forceinline__ void cp_commit(){ asm volatile("cp.async.commit_group;" ::: "memory"); }
__device__ __forceinline__ void cp_wait0(){ asm volatile("cp.async.wait_group 0;" ::: "memory"); }
__device__ __forceinline__ void cp_wait1(){ asm volatile("cp.async.wait_group 1;" ::: "memory"); }

__device__ __forceinline__ void mma16816(float* d, const unsigned* a, unsigned b0, unsigned b1){
    asm volatile(
      "mma.sync.aligned.m16n8k16.row.col.f32.bf16.bf16.f32 "
      "{%0,%1,%2,%3}, {%4,%5,%6,%7}, {%8,%9}, {%0,%1,%2,%3};\n"
      : "+f"(d[0]), "+f"(d[1]), "+f"(d[2]), "+f"(d[3])
      : "r"(a[0]), "r"(a[1]), "r"(a[2]), "r"(a[3]), "r"(b0), "r"(b1));
}

// ================= prep: pack W1 -> [kt][n][64B] bf16 rows ================
__global__ void k_prep(const float* __restrict__ W1){
    int idx = blockIdx.x*256 + threadIdx.x;    // 262144 words
    if (idx == 0){ g_first = 0x7fffffff; g_last = -1; }
    if (idx >= NKT*FF*(BK/2)) return;
    int kt = idx >> 13;          // 8192 words per ktile
    int wo = idx & 8191;
    int n  = wo >> 4;
    int ww = wo & 15;
    int k  = kt*BK + 2*ww;
    unsigned short lo = __bfloat16_as_ushort(__float2bfloat16(W1[(size_t)k*FF + n]));
    unsigned short hi = __bfloat16_as_ushort(__float2bfloat16(W1[(size_t)(k+1)*FF + n]));
    g_Bpk[idx] = ((uint32_t)hi << 16) | (uint32_t)lo;
}

// ===== k_cos: norms + adjacent dots + f32->bf16 tile-linear conversion =====
__global__ __launch_bounds__(256) void k_cos(const float* __restrict__ X){
    int tid = threadIdx.x, w = tid>>5, lane = tid&31;
    int base = blockIdx.x*32 + w*4;
    const float4* xp = (const float4*)X;
    float4 a[8];
    size_t rb = (size_t)base*(DD/4);
    #pragma unroll
    for (int t = 0; t < 8; t++) a[t] = xp[rb + lane + t*32];
    #pragma unroll
    for (int j = 0; j < 4; j++){
        int s = base + j;
        // write bf16 copy of row s (tile-linear layout: 8 uint2 per 64B k-tile seg)
        {
            int mtile = s >> 7, rl = s & 127;
            #pragma unroll
            for (int t = 0; t < 8; t++){
                int kt = 4*t + (lane>>3);
                __nv_bfloat162 p0 = __float22bfloat162_rn(make_float2(a[t].x, a[t].y));
                __nv_bfloat162 p1 = __float22bfloat162_rn(make_float2(a[t].z, a[t].w));
                size_t di = ((size_t)(mtile*NKT + kt)*128 + rl)*8 + (lane&7);
                g_Xb[di] = make_uint2(*(uint32_t*)&p0, *(uint32_t*)&p1);
            }
        }
        float n2 = 0.f;
        #pragma unroll
        for (int t = 0; t < 8; t++)
            n2 += a[t].x*a[t].x + a[t].y*a[t].y + a[t].z*a[t].z + a[t].w*a[t].w;
        bool pv = ((s & (SS-1)) != (SS-1));
        float4 b[8];
        float dt = 0.f;
        if (pv){
            size_t rb2 = (size_t)(s+1)*(DD/4);
            #pragma unroll
            for (int t = 0; t < 8; t++){
                b[t] = xp[rb2 + lane + t*32];
                dt += a[t].x*b[t].x + a[t].y*b[t].y + a[t].z*b[t].z + a[t].w*b[t].w;
            }
        }
        #pragma unroll
        for (int o = 16; o > 0; o >>= 1){
            n2 += __shfl_xor_sync(0xffffffffu, n2, o);
            dt += __shfl_xor_sync(0xffffffffu, dt, o);
        }
        if (lane == 0){ g_norm2[s] = n2; if (pv) g_dot[s] = dt; }
        #pragma unroll
        for (int t = 0; t < 8; t++) a[t] = b[t];
    }
}

// ================= GEMM: double-buffered cp.async + HMMA ==================
// per CTA: 128 rows x 128 cols, k-tiles of 32. smem rows padded 64->80 B.
#define ROWB 80
__global__ __launch_bounds__(256) void k_gemm(const float* __restrict__ b1,
                                              const float* __restrict__ w2){
    __shared__ __align__(16) char As[2][128*ROWB];
    __shared__ __align__(16) char Bs[2][128*ROWB];
    __shared__ float b1s[FF], w2s[FF];

    const int nc  = blockIdx.x;          // 0..3
    const int mt0 = blockIdx.y;          // m-tile id (128 rows)
    const int m0  = mt0 * 128;
    const int n0  = nc * 128;
    const int tid = threadIdx.x;
    const int warp = tid >> 5, lane = tid & 31;
    const int warpM = warp >> 1, warpN = warp & 1;
    const int lr = lane >> 2, qc = lane & 3;

    #pragma unroll
    for (int j = 0; j < 2; j++){
        b1s[tid + j*256] = b1[tid + j*256];
        w2s[tid + j*256] = w2[tid + j*256];
    }

    const uint32_t as0 = s2u(As[0]), as1 = s2u(As[1]);
    const uint32_t bs0 = s2u(Bs[0]), bs1 = s2u(Bs[1]);

    const char* xsrc = (const char*)g_Xb + (size_t)mt0 * (NKT*128*64);
    const char* bsrc = (const char*)g_Bpk;

    auto stage = [&](int kt, int buf){
        uint32_t ad = buf ? as1 : as0;
        uint32_t bd = buf ? bs1 : bs0;
        const char* xs = xsrc + (size_t)kt*(128*64);
        const char* bs = bsrc + ((size_t)kt*512 + n0)*64;
        #pragma unroll
        for (int i = 0; i < 2; i++){
            int g = tid + i*256;
            int row = g >> 2, cb = (g & 3)*16;
            cp16(ad + row*ROWB + cb, xs + row*64 + cb);
        }
        #pragma unroll
        for (int i = 0; i < 2; i++){
            int g = tid + i*256;
            int row = g >> 2, cb = (g & 3)*16;
            cp16(bd + row*ROWB + cb, bs + row*64 + cb);
        }
    };

    float acc[2][8][4];
    #pragma unroll
    for (int mt=0; mt<2; mt++)
      #pragma unroll
      for (int nt=0; nt<8; nt++)
        #pragma unroll
        for (int e=0; e<4; e++) acc[mt][nt][e] = 0.f;

    stage(0, 0);
    cp_commit();

    for (int kt = 0; kt < NKT; kt++){
        int cur = kt & 1;
        if (kt + 1 < NKT){
            stage(kt + 1, cur ^ 1);
            cp_commit();
            cp_wait1();
        } else {
            cp_wait0();
        }
        __syncthreads();
        const char* Ab = As[cur];
        const char* Bb = Bs[cur];
        #pragma unroll
        for (int ks = 0; ks < 2; ks++){
            unsigned int a[2][4];
            #pragma unroll
            for (int mt = 0; mt < 2; mt++){
                const char* basep = Ab + (warpM*32 + mt*16 + lr)*ROWB + ks*32 + qc*4;
                a[mt][0] = *(const unsigned int*)(basep);
                a[mt][1] = *(const unsigned int*)(basep + 8*ROWB);
                a[mt][2] = *(const unsigned int*)(basep + 16);
                a[mt][3] = *(const unsigned int*)(basep + 8*ROWB + 16);
            }
            #pragma unroll
            for (int nt = 0; nt < 8; nt++){
                int ncol = warpN*64 + nt*8 + lr;
                const char* bp = Bb + ncol*ROWB + ks*32 + qc*4;
                unsigned int bb0 = *(const unsigned int*)(bp);
                unsigned int bb1 = *(const unsigned int*)(bp + 16);
                mma16816(acc[0][nt], a[0], bb0, bb1);
                mma16816(acc[1][nt], a[1], bb0, bb1);
            }
        }
        __syncthreads();
    }

    // epilogue: per-row partial of relu(h+b1)*w2 over this CTA's 128 cols
    float b1r[16], w2r[16];
    #pragma unroll
    for (int nt = 0; nt < 8; nt++){
        #pragma unroll
        for (int e = 0; e < 2; e++){
            int n = n0 + warpN*64 + nt*8 + qc*2 + e;
            b1r[nt*2+e] = b1s[n];
            w2r[nt*2+e] = w2s[n];
        }
    }
    #pragma unroll
    for (int mt = 0; mt < 2; mt++){
        float sA = 0.f, sB = 0.f;
        #pragma unroll
        for (int nt = 0; nt < 8; nt++){
            #pragma unroll
            for (int e = 0; e < 2; e++){
                float bv = b1r[nt*2+e], wv = w2r[nt*2+e];
                sA += fmaxf(acc[mt][nt][e]   + bv, 0.f) * wv;
                sB += fmaxf(acc[mt][nt][2+e] + bv, 0.f) * wv;
            }
        }
        sA += __shfl_xor_sync(0xffffffffu, sA, 1);
        sA += __shfl_xor_sync(0xffffffffu, sA, 2);
        sB += __shfl_xor_sync(0xffffffffu, sB, 1);
        sB += __shfl_xor_sync(0xffffffffu, sB, 2);
        if (qc == 0){
            int rA = m0 + warpM*32 + mt*16 + lr;
            g_partial[(size_t)rA*8     + nc*2 + warpN] = sA;
            g_partial[(size_t)(rA+8)*8 + nc*2 + warpN] = sB;
        }
    }
}

// ================= scores: sigmoid(b2 + sum partials) ======================
__global__ void k_score(const float* __restrict__ b2){
    int i = blockIdx.x*256 + threadIdx.x;
    if (i < M_TOTAL){
        float l = b2[0];
        #pragma unroll
        for (int j = 0; j < 8; j++) l += g_partial[(size_t)i*8 + j];
        g_scores[i] = 1.f / (1.f + expf(-l));
    }
}

// ================= EOS rules + global bounds ===============================
__global__ void k_rule(){
    int i = blockIdx.x*256 + threadIdx.x;
    if (i >= M_TOTAL) return;
    int t = i & (SS-1);
    if (t < 2) return;
    float sc = g_scores[i];
    bool run = (sc > 0.7f) && (g_scores[i-1] > 0.7f) && (g_scores[i-2] > 0.7f);
    float na = fmaxf(sqrtf(g_norm2[i-1]), 1e-8f);
    float nb = fmaxf(sqrtf(g_norm2[i]),   1e-8f);
    float cosv = g_dot[i-1] / (na * nb);
    bool cr = (cosv < 0.3f) && (sc > 0.5f);
    if (run || cr){
        atomicMin(&g_first, t);
        atomicMax(&g_last,  t);
    }
}

// ================= segment pooling (early-exit prefix scan) ================
__global__ void k_pool(const float* __restrict__ X, const int* __restrict__ Mk){
    __shared__ float ssum[MAXP*DD];
    __shared__ int   scnt[MAXP];
    int b = blockIdx.x;
    int tid = threadIdx.x;            // 256
    for (int i = tid; i < MAXP*DD; i += 256) ssum[i] = 0.f;
    if (tid < MAXP) scnt[tid] = 0;
    __syncthreads();
    const float* xb = X + (size_t)b*SS*DD;
    const int*   mb = Mk + (size_t)b*SS;
    int c = 0;
    for (int s = 0; s < SS && c < MAXP; s++){
        #pragma unroll
        for (int j = 0; j < 4; j++){
            int d = tid + j*256;
            ssum[c*DD + d] += xb[(size_t)s*DD + d];
        }
        if (tid == 0) scnt[c]++;
        c += (mb[s] != 0) ? 1 : 0;
    }
    __syncthreads();
    #pragma unroll
    for (int p = 0; p < MAXP; p++){
        float inv = 1.f / (float)max(scnt[p], 1);
        #pragma unroll
        for (int j = 0; j < 4; j++){
            int d = tid + j*256;
            g_pooled[((size_t)b*MAXP + p)*DD + d] = ssum[p*DD + d] * inv;
        }
    }
}

// ================= patches = pooled @ proj_w + proj_b ======================
__global__ void k_patch(const float* __restrict__ Pw, const float* __restrict__ Pb,
                        float* __restrict__ out){
    __shared__ float ps[MAXP*DD];
    int oc = blockIdx.x, b = blockIdx.y;
    int tid = threadIdx.x;            // 128
    for (int i = tid; i < MAXP*DD; i += 128) ps[i] = g_pooled[(size_t)b*MAXP*DD + i];
    __syncthreads();
    int o = oc*128 + tid;
    float acc[MAXP];
    #pragma unroll
    for (int p = 0; p < MAXP; p++) acc[p] = 0.f;
    for (int d = 0; d < DD; d++){
        float w = Pw[(size_t)d*DD + o];
        #pragma unroll
        for (int p = 0; p < MAXP; p++) acc[p] += ps[p*DD + d] * w;
    }
    float bias = Pb[o];
    #pragma unroll
    for (int p = 0; p < MAXP; p++)
        out[((size_t)b*MAXP + p)*DD + o] = acc[p] + bias;
}

// ================= finalize bounds =========================================
__global__ void k_final(float* __restrict__ out, int out_size){
    if (threadIdx.x == 0 && blockIdx.x == 0){
        int f = g_first, l = g_last;
        float s0 = -1.f, s1 = -1.f;
        if (f != 0x7fffffff){
            s0 = (float)max(0, f - 2);
            s1 = (float)min(SS - 1, l + 2);
        }
        if (out_size >= BB*MAXP*DD + 2){
            out[BB*MAXP*DD + 0] = s0;
            out[BB*MAXP*DD + 1] = s1;
        }
    }
}

// ===========================================================================
extern "C" void kernel_launch(void* const* d_in, const int* in_sizes, int n_in,
                              void* d_out, int out_size) {
    const float* latent = (const float*)d_in[0];
    const int*   mask   = (const int*)  d_in[1];
    const float* proj_w = (const float*)d_in[2];
    const float* proj_b = (const float*)d_in[3];
    const float* w1     = (const float*)d_in[4];
    const float* b1     = (const float*)d_in[5];
    const float* w2     = (const float*)d_in[6];
    const float* b2     = (const float*)d_in[7];
    float* out = (float*)d_out;

    k_prep <<< (NKT*FF*(BK/2) + 255)/256, 256 >>>(w1);
    k_cos  <<< M_TOTAL/32, 256 >>>(latent);
    k_gemm <<< dim3(4, M_TOTAL/128), 256 >>>(b1, w2);
    k_score<<< M_TOTAL/256, 256 >>>(b2);
    k_rule <<< M_TOTAL/256, 256 >>>();
    k_pool <<< BB, 256 >>>(latent, mask);
    k_patch<<< dim3(DD/128, BB), 128 >>>(proj_w, proj_b, out);
    k_final<<< 1, 32 >>>(out, out_size);
}

// round 7
// speedup vs baseline: 1.3200x; 1.3200x over previous
#include <cuda_runtime.h>
#include <cuda_bf16.h>
#include <cuda_fp8.h>
#include <math.h>
#include <stdint.h>

#define BB 8
#define SS 4096
#define DD 1024
#define FF 512
#define M_TOTAL (BB*SS)   // 32768
#define MAXP 8
#define NKT 16            // 1024/64 k-tiles
#define W1SCALE 64.0f
#define W1INV   0.015625f

// ---------------- device scratch ----------------
// X as e4m3, tile-linear: [mtile 0..255][kt 0..15][row 0..127][64 B]
__device__ uint32_t g_Xq[(size_t)M_TOTAL * (DD/4)];      // 32 MB
// 64*W1 as e4m3, tile-linear: [kt 0..15][n 0..511][64 B]
__device__ uint32_t g_Bpk[NKT * FF * 16];                // 512 KB
__device__ float g_partial[M_TOTAL*8];
__device__ float g_scores[M_TOTAL];
__device__ float g_norm2[M_TOTAL];
__device__ float g_dot[M_TOTAL];
__device__ float g_pooled[BB*MAXP*DD];
__device__ int g_first, g_last;

// ---------------- helpers ----------------
__device__ __forceinline__ uint32_t s2u(const void* p){
    uint32_t a;
    asm("{ .reg .u64 t; cvta.to.shared.u64 t, %1; cvt.u32.u64 %0, t; }" : "=r"(a) : "l"(p));
    return a;
}
__device__ __forceinline__ void cp16(uint32_t dst, const void* src){
    asm volatile("cp.async.cg.shared.global [%0], [%1], 16;" :: "r"(dst), "l"(src) : "memory");
}
__device__ __forceinline__ void cp_commit(){ asm volatile("cp.async.commit_group;" ::: "memory"); }
__device__ __forceinline__ void cp_wait0(){ asm volatile("cp.async.wait_group 0;" ::: "memory"); }
__device__ __forceinline__ void cp_wait1(){ asm volatile("cp.async.wait_group 1;" ::: "memory"); }

// fp8 e4m3 m16n8k32 MMA, f32 accum
__device__ __forceinline__ void mmaq(float* d, const unsigned* a, unsigned b0, unsigned b1){
    asm volatile(
      "mma.sync.aligned.m16n8k32.row.col.f32.e4m3.e4m3.f32 "
      "{%0,%1,%2,%3}, {%4,%5,%6,%7}, {%8,%9}, {%0,%1,%2,%3};\n"
      : "+f"(d[0]), "+f"(d[1]), "+f"(d[2]), "+f"(d[3])
      : "r"(a[0]), "r"(a[1]), "r"(a[2]), "r"(a[3]), "r"(b0), "r"(b1));
}

__device__ __forceinline__ uint32_t pack4_e4m3(float x, float y, float z, float w){
    __nv_fp8x2_storage_t p0 = __nv_cvt_float2_to_fp8x2(make_float2(x, y), __NV_SATFINITE, __NV_E4M3);
    __nv_fp8x2_storage_t p1 = __nv_cvt_float2_to_fp8x2(make_float2(z, w), __NV_SATFINITE, __NV_E4M3);
    return ((uint32_t)p1 << 16) | (uint32_t)p0;
}

// ================= prep: pack 64*W1 -> [kt][n][64B] e4m3 rows =============
__global__ void k_prep(const float* __restrict__ W1){
    int idx = blockIdx.x*256 + threadIdx.x;    // 131072 words
    if (idx == 0){ g_first = 0x7fffffff; g_last = -1; }
    if (idx >= NKT*FF*16) return;
    int kt = idx >> 13;          // 8192 words per ktile
    int wo = idx & 8191;
    int n  = wo >> 4;
    int ww = wo & 15;
    int k  = kt*64 + 4*ww;
    g_Bpk[idx] = pack4_e4m3(W1[(size_t)k*FF + n]     * W1SCALE,
                            W1[(size_t)(k+1)*FF + n] * W1SCALE,
                            W1[(size_t)(k+2)*FF + n] * W1SCALE,
                            W1[(size_t)(k+3)*FF + n] * W1SCALE);
}

// ===== k_cos: norms + adjacent dots + f32->e4m3 tile-linear conversion =====
__global__ __launch_bounds__(256) void k_cos(const float* __restrict__ X){
    int tid = threadIdx.x, w = tid>>5, lane = tid&31;
    int base = blockIdx.x*32 + w*4;
    const float4* xp = (const float4*)X;
    float4 a[8];
    size_t rb = (size_t)base*(DD/4);
    #pragma unroll
    for (int t = 0; t < 8; t++) a[t] = xp[rb + lane + t*32];
    #pragma unroll
    for (int j = 0; j < 4; j++){
        int s = base + j;
        // write e4m3 copy of row s (tile-linear)
        {
            int mtile = s >> 7, rl = s & 127;
            #pragma unroll
            for (int t = 0; t < 8; t++){
                // this float4 covers cols 4*(lane + 32t) .. +3
                int kt = (lane >> 4) + 2*t;            // col/64
                int wi = lane & 15;                    // word within 64B row
                uint32_t q = pack4_e4m3(a[t].x, a[t].y, a[t].z, a[t].w);
                size_t di = ((size_t)(mtile*NKT + kt)*128 + rl)*16 + wi;
                g_Xq[di] = q;
            }
        }
        float n2 = 0.f;
        #pragma unroll
        for (int t = 0; t < 8; t++)
            n2 += a[t].x*a[t].x + a[t].y*a[t].y + a[t].z*a[t].z + a[t].w*a[t].w;
        bool pv = ((s & (SS-1)) != (SS-1));
        float4 b[8];
        float dt = 0.f;
        if (pv){
            size_t rb2 = (size_t)(s+1)*(DD/4);
            #pragma unroll
            for (int t = 0; t < 8; t++){
                b[t] = xp[rb2 + lane + t*32];
                dt += a[t].x*b[t].x + a[t].y*b[t].y + a[t].z*b[t].z + a[t].w*b[t].w;
            }
        }
        #pragma unroll
        for (int o = 16; o > 0; o >>= 1){
            n2 += __shfl_xor_sync(0xffffffffu, n2, o);
            dt += __shfl_xor_sync(0xffffffffu, dt, o);
        }
        if (lane == 0){ g_norm2[s] = n2; if (pv) g_dot[s] = dt; }
        #pragma unroll
        for (int t = 0; t < 8; t++) a[t] = b[t];
    }
}

// ================= GEMM: double-buffered cp.async + fp8 QMMA ==============
// per CTA: 128 rows x 128 cols, k-tiles of 64 (e4m3). smem rows 64->80 B.
#define ROWB 80
__global__ __launch_bounds__(256) void k_gemm(const float* __restrict__ b1,
                                              const float* __restrict__ w2){
    __shared__ __align__(16) char As[2][128*ROWB];
    __shared__ __align__(16) char Bs[2][128*ROWB];
    __shared__ float b1s[FF], w2s[FF];

    const int nc  = blockIdx.x;          // 0..3
    const int mt0 = blockIdx.y;          // m-tile id (128 rows)
    const int m0  = mt0 * 128;
    const int n0  = nc * 128;
    const int tid = threadIdx.x;
    const int warp = tid >> 5, lane = tid & 31;
    const int warpM = warp >> 1, warpN = warp & 1;
    const int lr = lane >> 2, qc = lane & 3;

    #pragma unroll
    for (int j = 0; j < 2; j++){
        b1s[tid + j*256] = b1[tid + j*256];
        w2s[tid + j*256] = w2[tid + j*256];
    }

    const uint32_t as0 = s2u(As[0]), as1 = s2u(As[1]);
    const uint32_t bs0 = s2u(Bs[0]), bs1 = s2u(Bs[1]);

    const char* xsrc = (const char*)g_Xq + (size_t)mt0 * (NKT*128*64);
    const char* bsrc = (const char*)g_Bpk;

    auto stage = [&](int kt, int buf){
        uint32_t ad = buf ? as1 : as0;
        uint32_t bd = buf ? bs1 : bs0;
        const char* xs = xsrc + (size_t)kt*(128*64);
        const char* bs = bsrc + ((size_t)kt*512 + n0)*64;
        #pragma unroll
        for (int i = 0; i < 2; i++){
            int g = tid + i*256;
            int row = g >> 2, cb = (g & 3)*16;
            cp16(ad + row*ROWB + cb, xs + row*64 + cb);
        }
        #pragma unroll
        for (int i = 0; i < 2; i++){
            int g = tid + i*256;
            int row = g >> 2, cb = (g & 3)*16;
            cp16(bd + row*ROWB + cb, bs + row*64 + cb);
        }
    };

    float acc[2][8][4];
    #pragma unroll
    for (int mt=0; mt<2; mt++)
      #pragma unroll
      for (int nt=0; nt<8; nt++)
        #pragma unroll
        for (int e=0; e<4; e++) acc[mt][nt][e] = 0.f;

    stage(0, 0);
    cp_commit();

    for (int kt = 0; kt < NKT; kt++){
        int cur = kt & 1;
        if (kt + 1 < NKT){
            stage(kt + 1, cur ^ 1);
            cp_commit();
            cp_wait1();
        } else {
            cp_wait0();
        }
        __syncthreads();
        const char* Ab = As[cur];
        const char* Bb = Bs[cur];
        #pragma unroll
        for (int ks = 0; ks < 2; ks++){   // two k32 windows within 64B row
            unsigned int a[2][4];
            #pragma unroll
            for (int mt = 0; mt < 2; mt++){
                const char* basep = Ab + (warpM*32 + mt*16 + lr)*ROWB + ks*32 + qc*4;
                a[mt][0] = *(const unsigned int*)(basep);
                a[mt][1] = *(const unsigned int*)(basep + 8*ROWB);
                a[mt][2] = *(const unsigned int*)(basep + 16);
                a[mt][3] = *(const unsigned int*)(basep + 8*ROWB + 16);
            }
            #pragma unroll
            for (int nt = 0; nt < 8; nt++){
                int ncol = warpN*64 + nt*8 + lr;
                const char* bp = Bb + ncol*ROWB + ks*32 + qc*4;
                unsigned int bb0 = *(const unsigned int*)(bp);
                unsigned int bb1 = *(const unsigned int*)(bp + 16);
                mmaq(acc[0][nt], a[0], bb0, bb1);
                mmaq(acc[1][nt], a[1], bb0, bb1);
            }
        }
        __syncthreads();
    }

    // epilogue: per-row partial of relu(acc/64 + b1)*w2 over this CTA's 128 cols
    float b1r[16], w2r[16];
    #pragma unroll
    for (int nt = 0; nt < 8; nt++){
        #pragma unroll
        for (int e = 0; e < 2; e++){
            int n = n0 + warpN*64 + nt*8 + qc*2 + e;
            b1r[nt*2+e] = b1s[n];
            w2r[nt*2+e] = w2s[n];
        }
    }
    #pragma unroll
    for (int mt = 0; mt < 2; mt++){
        float sA = 0.f, sB = 0.f;
        #pragma unroll
        for (int nt = 0; nt < 8; nt++){
            #pragma unroll
            for (int e = 0; e < 2; e++){
                float bv = b1r[nt*2+e], wv = w2r[nt*2+e];
                sA += fmaxf(acc[mt][nt][e]   * W1INV + bv, 0.f) * wv;
                sB += fmaxf(acc[mt][nt][2+e] * W1INV + bv, 0.f) * wv;
            }
        }
        sA += __shfl_xor_sync(0xffffffffu, sA, 1);
        sA += __shfl_xor_sync(0xffffffffu, sA, 2);
        sB += __shfl_xor_sync(0xffffffffu, sB, 1);
        sB += __shfl_xor_sync(0xffffffffu, sB, 2);
        if (qc == 0){
            int rA = m0 + warpM*32 + mt*16 + lr;
            g_partial[(size_t)rA*8     + nc*2 + warpN] = sA;
            g_partial[(size_t)(rA+8)*8 + nc*2 + warpN] = sB;
        }
    }
}

// ================= scores: sigmoid(b2 + sum partials) ======================
__global__ void k_score(const float* __restrict__ b2){
    int i = blockIdx.x*256 + threadIdx.x;
    if (i < M_TOTAL){
        float l = b2[0];
        #pragma unroll
        for (int j = 0; j < 8; j++) l += g_partial[(size_t)i*8 + j];
        g_scores[i] = 1.f / (1.f + expf(-l));
    }
}

// ================= EOS rules + global bounds ===============================
__global__ void k_rule(){
    int i = blockIdx.x*256 + threadIdx.x;
    if (i >= M_TOTAL) return;
    int t = i & (SS-1);
    if (t < 2) return;
    float sc = g_scores[i];
    bool run = (sc > 0.7f) && (g_scores[i-1] > 0.7f) && (g_scores[i-2] > 0.7f);
    float na = fmaxf(sqrtf(g_norm2[i-1]), 1e-8f);
    float nb = fmaxf(sqrtf(g_norm2[i]),   1e-8f);
    float cosv = g_dot[i-1] / (na * nb);
    bool cr = (cosv < 0.3f) && (sc > 0.5f);
    if (run || cr){
        atomicMin(&g_first, t);
        atomicMax(&g_last,  t);
    }
}

// ================= segment pooling (early-exit prefix scan) ================
__global__ void k_pool(const float* __restrict__ X, const int* __restrict__ Mk){
    __shared__ float ssum[MAXP*DD];
    __shared__ int   scnt[MAXP];
    int b = blockIdx.x;
    int tid = threadIdx.x;            // 256
    for (int i = tid; i < MAXP*DD; i += 256) ssum[i] = 0.f;
    if (tid < MAXP) scnt[tid] = 0;
    __syncthreads();
    const float* xb = X + (size_t)b*SS*DD;
    const int*   mb = Mk + (size_t)b*SS;
    int c = 0;
    for (int s = 0; s < SS && c < MAXP; s++){
        #pragma unroll
        for (int j = 0; j < 4; j++){
            int d = tid + j*256;
            ssum[c*DD + d] += xb[(size_t)s*DD + d];
        }
        if (tid == 0) scnt[c]++;
        c += (mb[s] != 0) ? 1 : 0;
    }
    __syncthreads();
    #pragma unroll
    for (int p = 0; p < MAXP; p++){
        float inv = 1.f / (float)max(scnt[p], 1);
        #pragma unroll
        for (int j = 0; j < 4; j++){
            int d = tid + j*256;
            g_pooled[((size_t)b*MAXP + p)*DD + d] = ssum[p*DD + d] * inv;
        }
    }
}

// ================= patches = pooled @ proj_w + proj_b ======================
__global__ void k_patch(const float* __restrict__ Pw, const float* __restrict__ Pb,
                        float* __restrict__ out){
    __shared__ float ps[MAXP*DD];
    int oc = blockIdx.x, b = blockIdx.y;
    int tid = threadIdx.x;            // 128
    for (int i = tid; i < MAXP*DD; i += 128) ps[i] = g_pooled[(size_t)b*MAXP*DD + i];
    __syncthreads();
    int o = oc*128 + tid;
    float acc[MAXP];
    #pragma unroll
    for (int p = 0; p < MAXP; p++) acc[p] = 0.f;
    for (int d = 0; d < DD; d++){
        float w = Pw[(size_t)d*DD + o];
        #pragma unroll
        for (int p = 0; p < MAXP; p++) acc[p] += ps[p*DD + d] * w;
    }
    float bias = Pb[o];
    #pragma unroll
    for (int p = 0; p < MAXP; p++)
        out[((size_t)b*MAXP + p)*DD + o] = acc[p] + bias;
}

// ================= finalize bounds =========================================
__global__ void k_final(float* __restrict__ out, int out_size){
    if (threadIdx.x == 0 && blockIdx.x == 0){
        int f = g_first, l = g_last;
        float s0 = -1.f, s1 = -1.f;
        if (f != 0x7fffffff){
            s0 = (float)max(0, f - 2);
            s1 = (float)min(SS - 1, l + 2);
        }
        if (out_size >= BB*MAXP*DD + 2){
            out[BB*MAXP*DD + 0] = s0;
            out[BB*MAXP*DD + 1] = s1;
        }
    }
}

// ===========================================================================
extern "C" void kernel_launch(void* const* d_in, const int* in_sizes, int n_in,
                              void* d_out, int out_size) {
    const float* latent = (const float*)d_in[0];
    const int*   mask   = (const int*)  d_in[1];
    const float* proj_w = (const float*)d_in[2];
    const float* proj_b = (const float*)d_in[3];
    const float* w1     = (const float*)d_in[4];
    const float* b1     = (const float*)d_in[5];
    const float* w2     = (const float*)d_in[6];
    const float* b2     = (const float*)d_in[7];
    float* out = (float*)d_out;

    k_prep <<< (NKT*FF*16 + 255)/256, 256 >>>(w1);
    k_cos  <<< M_TOTAL/32, 256 >>>(latent);
    k_gemm <<< dim3(4, M_TOTAL/128), 256 >>>(b1, w2);
    k_score<<< M_TOTAL/256, 256 >>>(b2);
    k_rule <<< M_TOTAL/256, 256 >>>();
    k_pool <<< BB, 256 >>>(latent, mask);
    k_patch<<< dim3(DD/128, BB), 128 >>>(proj_w, proj_b, out);
    k_final<<< 1, 32 >>>(out, out_size);
}

// round 8
// speedup vs baseline: 1.3500x; 1.0227x over previous
#include <cuda_runtime.h>
#include <cuda_bf16.h>
#include <cuda_fp8.h>
#include <math.h>
#include <stdint.h>

#define BB 8
#define SS 4096
#define DD 1024
#define FF 512
#define M_TOTAL (BB*SS)   // 32768
#define MAXP 8
#define NKT 16            // 1024/64 k-tiles
#define W1SCALE 64.0f
#define W1INV   0.015625f

// ---------------- device scratch ----------------
// X as e4m3, tile-linear: [mtile 0..255][kt 0..15][row 0..127][64 B]
__device__ uint32_t g_Xq[(size_t)M_TOTAL * (DD/4)];      // 32 MB
// 64*W1 as e4m3, tile-linear: [kt 0..15][n 0..511][64 B]
__device__ uint32_t g_Bpk[NKT * FF * 16];                // 512 KB
__device__ float g_partial[M_TOTAL*8];
__device__ float g_scores[M_TOTAL];
__device__ float g_norm2[M_TOTAL];
__device__ float g_dot[M_TOTAL];
__device__ float g_pooled[BB*MAXP*DD];
__device__ int g_first, g_last;

// ---------------- helpers ----------------
__device__ __forceinline__ uint32_t s2u(const void* p){
    uint32_t a;
    asm("{ .reg .u64 t; cvta.to.shared.u64 t, %1; cvt.u32.u64 %0, t; }" : "=r"(a) : "l"(p));
    return a;
}
__device__ __forceinline__ void cp16(uint32_t dst, const void* src){
    asm volatile("cp.async.cg.shared.global [%0], [%1], 16;" :: "r"(dst), "l"(src) : "memory");
}
__device__ __forceinline__ void cp_commit(){ asm volatile("cp.async.commit_group;" ::: "memory"); }
__device__ __forceinline__ void cp_wait0(){ asm volatile("cp.async.wait_group 0;" ::: "memory"); }
__device__ __forceinline__ void cp_wait1(){ asm volatile("cp.async.wait_group 1;" ::: "memory"); }

// fp8 e4m3 m16n8k32 MMA, f32 accum
__device__ __forceinline__ void mmaq(float* d, const unsigned* a, unsigned b0, unsigned b1){
    asm volatile(
      "mma.sync.aligned.m16n8k32.row.col.f32.e4m3.e4m3.f32 "
      "{%0,%1,%2,%3}, {%4,%5,%6,%7}, {%8,%9}, {%0,%1,%2,%3};\n"
      : "+f"(d[0]), "+f"(d[1]), "+f"(d[2]), "+f"(d[3])
      : "r"(a[0]), "r"(a[1]), "r"(a[2]), "r"(a[3]), "r"(b0), "r"(b1));
}

// ldmatrix x4 (b16 tiles; bytes are dtype-agnostic)
__device__ __forceinline__ void ldsm4(unsigned* r, uint32_t addr){
    asm volatile("ldmatrix.sync.aligned.m8n8.x4.shared.b16 {%0,%1,%2,%3}, [%4];"
                 : "=r"(r[0]), "=r"(r[1]), "=r"(r[2]), "=r"(r[3]) : "r"(addr));
}

__device__ __forceinline__ uint32_t pack4_e4m3(float x, float y, float z, float w){
    __nv_fp8x2_storage_t p0 = __nv_cvt_float2_to_fp8x2(make_float2(x, y), __NV_SATFINITE, __NV_E4M3);
    __nv_fp8x2_storage_t p1 = __nv_cvt_float2_to_fp8x2(make_float2(z, w), __NV_SATFINITE, __NV_E4M3);
    return ((uint32_t)p1 << 16) | (uint32_t)p0;
}

// ================= prep: pack 64*W1 -> [kt][n][64B] e4m3 rows =============
__global__ void k_prep(const float* __restrict__ W1){
    int idx = blockIdx.x*256 + threadIdx.x;    // 131072 words
    if (idx == 0){ g_first = 0x7fffffff; g_last = -1; }
    if (idx >= NKT*FF*16) return;
    int kt = idx >> 13;          // 8192 words per ktile
    int wo = idx & 8191;
    int n  = wo >> 4;
    int ww = wo & 15;
    int k  = kt*64 + 4*ww;
    g_Bpk[idx] = pack4_e4m3(W1[(size_t)k*FF + n]     * W1SCALE,
                            W1[(size_t)(k+1)*FF + n] * W1SCALE,
                            W1[(size_t)(k+2)*FF + n] * W1SCALE,
                            W1[(size_t)(k+3)*FF + n] * W1SCALE);
}

// ===== k_cos: norms + adjacent dots + f32->e4m3 tile-linear conversion =====
__global__ __launch_bounds__(256) void k_cos(const float* __restrict__ X){
    int tid = threadIdx.x, w = tid>>5, lane = tid&31;
    int base = blockIdx.x*32 + w*4;
    const float4* xp = (const float4*)X;
    float4 a[8];
    size_t rb = (size_t)base*(DD/4);
    #pragma unroll
    for (int t = 0; t < 8; t++) a[t] = xp[rb + lane + t*32];
    #pragma unroll
    for (int j = 0; j < 4; j++){
        int s = base + j;
        // write e4m3 copy of row s (tile-linear)
        {
            int mtile = s >> 7, rl = s & 127;
            #pragma unroll
            for (int t = 0; t < 8; t++){
                int kt = (lane >> 4) + 2*t;            // col/64
                int wi = lane & 15;                    // word within 64B row
                uint32_t q = pack4_e4m3(a[t].x, a[t].y, a[t].z, a[t].w);
                size_t di = ((size_t)(mtile*NKT + kt)*128 + rl)*16 + wi;
                g_Xq[di] = q;
            }
        }
        float n2 = 0.f;
        #pragma unroll
        for (int t = 0; t < 8; t++)
            n2 += a[t].x*a[t].x + a[t].y*a[t].y + a[t].z*a[t].z + a[t].w*a[t].w;
        bool pv = ((s & (SS-1)) != (SS-1));
        float4 b[8];
        float dt = 0.f;
        if (pv){
            size_t rb2 = (size_t)(s+1)*(DD/4);
            #pragma unroll
            for (int t = 0; t < 8; t++){
                b[t] = xp[rb2 + lane + t*32];
                dt += a[t].x*b[t].x + a[t].y*b[t].y + a[t].z*b[t].z + a[t].w*b[t].w;
            }
        }
        #pragma unroll
        for (int o = 16; o > 0; o >>= 1){
            n2 += __shfl_xor_sync(0xffffffffu, n2, o);
            dt += __shfl_xor_sync(0xffffffffu, dt, o);
        }
        if (lane == 0){ g_norm2[s] = n2; if (pv) g_dot[s] = dt; }
        #pragma unroll
        for (int t = 0; t < 8; t++) a[t] = b[t];
    }
}

// ================= GEMM: double-buffered cp.async + fp8 QMMA + LDSM =======
// per CTA: 128 rows x 128 cols, k-tiles of 64 (e4m3). smem rows 64->80 B.
#define ROWB 80
__global__ __launch_bounds__(256) void k_gemm(const float* __restrict__ b1,
                                              const float* __restrict__ w2){
    __shared__ __align__(16) char As[2][128*ROWB];
    __shared__ __align__(16) char Bs[2][128*ROWB];
    __shared__ float b1s[FF], w2s[FF];

    const int nc  = blockIdx.x;          // 0..3
    const int mt0 = blockIdx.y;          // m-tile id (128 rows)
    const int m0  = mt0 * 128;
    const int n0  = nc * 128;
    const int tid = threadIdx.x;
    const int warp = tid >> 5, lane = tid & 31;
    const int warpM = warp >> 1, warpN = warp & 1;
    const int lr = lane >> 2, qc = lane & 3;

    #pragma unroll
    for (int j = 0; j < 2; j++){
        b1s[tid + j*256] = b1[tid + j*256];
        w2s[tid + j*256] = w2[tid + j*256];
    }

    const uint32_t as0 = s2u(As[0]), as1 = s2u(As[1]);
    const uint32_t bs0 = s2u(Bs[0]), bs1 = s2u(Bs[1]);

    // per-lane ldmatrix source offsets (matrix order: {+0,+0},{+8r,+0},{+0,+16B},{+8r,+16B})
    const int arow = warpM*32 + (lane & 7) + ((lane >> 3) & 1)*8;
    const int abyt = ((lane >> 4) & 1)*16;
    const int brow = warpN*64 + (lane & 7) + ((lane >> 4) & 1)*8;
    const int bbyt = ((lane >> 3) & 1)*16;
    const uint32_t aoff = (uint32_t)(arow*ROWB + abyt);
    const uint32_t boff = (uint32_t)(brow*ROWB + bbyt);

    const char* xsrc = (const char*)g_Xq + (size_t)mt0 * (NKT*128*64);
    const char* bsrc = (const char*)g_Bpk;

    auto stage = [&](int kt, int buf){
        uint32_t ad = buf ? as1 : as0;
        uint32_t bd = buf ? bs1 : bs0;
        const char* xs = xsrc + (size_t)kt*(128*64);
        const char* bs = bsrc + ((size_t)kt*512 + n0)*64;
        #pragma unroll
        for (int i = 0; i < 2; i++){
            int g = tid + i*256;
            int row = g >> 2, cb = (g & 3)*16;
            cp16(ad + row*ROWB + cb, xs + row*64 + cb);
        }
        #pragma unroll
        for (int i = 0; i < 2; i++){
            int g = tid + i*256;
            int row = g >> 2, cb = (g & 3)*16;
            cp16(bd + row*ROWB + cb, bs + row*64 + cb);
        }
    };

    float acc[2][8][4];
    #pragma unroll
    for (int mt=0; mt<2; mt++)
      #pragma unroll
      for (int nt=0; nt<8; nt++)
        #pragma unroll
        for (int e=0; e<4; e++) acc[mt][nt][e] = 0.f;

    stage(0, 0);
    cp_commit();

    for (int kt = 0; kt < NKT; kt++){
        int cur = kt & 1;
        if (kt + 1 < NKT){
            stage(kt + 1, cur ^ 1);
            cp_commit();
            cp_wait1();
        } else {
            cp_wait0();
        }
        __syncthreads();
        const uint32_t aA = (cur ? as1 : as0) + aoff;
        const uint32_t bA = (cur ? bs1 : bs0) + boff;
        #pragma unroll
        for (int ks = 0; ks < 2; ks++){   // two k32 windows within 64B row
            unsigned int a[2][4];
            ldsm4(a[0], aA + ks*32);               // rows +0..15
            ldsm4(a[1], aA + 16*ROWB + ks*32);     // rows +16..31
            unsigned int b[8][2];
            #pragma unroll
            for (int ntp = 0; ntp < 4; ntp++){     // each covers nt=2*ntp, 2*ntp+1
                unsigned int r[4];
                ldsm4(r, bA + ntp*16*ROWB + ks*32);
                b[2*ntp  ][0] = r[0]; b[2*ntp  ][1] = r[1];
                b[2*ntp+1][0] = r[2]; b[2*ntp+1][1] = r[3];
            }
            #pragma unroll
            for (int nt = 0; nt < 8; nt++){
                mmaq(acc[0][nt], a[0], b[nt][0], b[nt][1]);
                mmaq(acc[1][nt], a[1], b[nt][0], b[nt][1]);
            }
        }
        __syncthreads();
    }

    // epilogue: per-row partial of relu(acc/64 + b1)*w2 over this CTA's 128 cols
    float b1r[16], w2r[16];
    #pragma unroll
    for (int nt = 0; nt < 8; nt++){
        #pragma unroll
        for (int e = 0; e < 2; e++){
            int n = n0 + warpN*64 + nt*8 + qc*2 + e;
            b1r[nt*2+e] = b1s[n];
            w2r[nt*2+e] = w2s[n];
        }
    }
    #pragma unroll
    for (int mt = 0; mt < 2; mt++){
        float sA = 0.f, sB = 0.f;
        #pragma unroll
        for (int nt = 0; nt < 8; nt++){
            #pragma unroll
            for (int e = 0; e < 2; e++){
                float bv = b1r[nt*2+e], wv = w2r[nt*2+e];
                sA += fmaxf(acc[mt][nt][e]   * W1INV + bv, 0.f) * wv;
                sB += fmaxf(acc[mt][nt][2+e] * W1INV + bv, 0.f) * wv;
            }
        }
        sA += __shfl_xor_sync(0xffffffffu, sA, 1);
        sA += __shfl_xor_sync(0xffffffffu, sA, 2);
        sB += __shfl_xor_sync(0xffffffffu, sB, 1);
        sB += __shfl_xor_sync(0xffffffffu, sB, 2);
        if (qc == 0){
            int rA = m0 + warpM*32 + mt*16 + lr;
            g_partial[(size_t)rA*8     + nc*2 + warpN] = sA;
            g_partial[(size_t)(rA+8)*8 + nc*2 + warpN] = sB;
        }
    }
}

// ================= scores: sigmoid(b2 + sum partials) ======================
__global__ void k_score(const float* __restrict__ b2){
    int i = blockIdx.x*256 + threadIdx.x;
    if (i < M_TOTAL){
        float l = b2[0];
        #pragma unroll
        for (int j = 0; j < 8; j++) l += g_partial[(size_t)i*8 + j];
        g_scores[i] = 1.f / (1.f + expf(-l));
    }
}

// ================= EOS rules + global bounds ===============================
__global__ void k_rule(){
    int i = blockIdx.x*256 + threadIdx.x;
    if (i >= M_TOTAL) return;
    int t = i & (SS-1);
    if (t < 2) return;
    float sc = g_scores[i];
    bool run = (sc > 0.7f) && (g_scores[i-1] > 0.7f) && (g_scores[i-2] > 0.7f);
    float na = fmaxf(sqrtf(g_norm2[i-1]), 1e-8f);
    float nb = fmaxf(sqrtf(g_norm2[i]),   1e-8f);
    float cosv = g_dot[i-1] / (na * nb);
    bool cr = (cosv < 0.3f) && (sc > 0.5f);
    if (run || cr){
        atomicMin(&g_first, t);
        atomicMax(&g_last,  t);
    }
}

// ================= segment pooling (early-exit prefix scan) ================
__global__ void k_pool(const float* __restrict__ X, const int* __restrict__ Mk){
    __shared__ float ssum[MAXP*DD];
    __shared__ int   scnt[MAXP];
    int b = blockIdx.x;
    int tid = threadIdx.x;            // 256
    for (int i = tid; i < MAXP*DD; i += 256) ssum[i] = 0.f;
    if (tid < MAXP) scnt[tid] = 0;
    __syncthreads();
    const float* xb = X + (size_t)b*SS*DD;
    const int*   mb = Mk + (size_t)b*SS;
    int c = 0;
    for (int s = 0; s < SS && c < MAXP; s++){
        #pragma unroll
        for (int j = 0; j < 4; j++){
            int d = tid + j*256;
            ssum[c*DD + d] += xb[(size_t)s*DD + d];
        }
        if (tid == 0) scnt[c]++;
        c += (mb[s] != 0) ? 1 : 0;
    }
    __syncthreads();
    #pragma unroll
    for (int p = 0; p < MAXP; p++){
        float inv = 1.f / (float)max(scnt[p], 1);
        #pragma unroll
        for (int j = 0; j < 4; j++){
            int d = tid + j*256;
            g_pooled[((size_t)b*MAXP + p)*DD + d] = ssum[p*DD + d] * inv;
        }
    }
}

// ================= patches = pooled @ proj_w + proj_b ======================
__global__ void k_patch(const float* __restrict__ Pw, const float* __restrict__ Pb,
                        float* __restrict__ out){
    __shared__ float ps[MAXP*DD];
    int oc = blockIdx.x, b = blockIdx.y;
    int tid = threadIdx.x;            // 128
    for (int i = tid; i < MAXP*DD; i += 128) ps[i] = g_pooled[(size_t)b*MAXP*DD + i];
    __syncthreads();
    int o = oc*128 + tid;
    float acc[MAXP];
    #pragma unroll
    for (int p = 0; p < MAXP; p++) acc[p] = 0.f;
    for (int d = 0; d < DD; d++){
        float w = Pw[(size_t)d*DD + o];
        #pragma unroll
        for (int p = 0; p < MAXP; p++) acc[p] += ps[p*DD + d] * w;
    }
    float bias = Pb[o];
    #pragma unroll
    for (int p = 0; p < MAXP; p++)
        out[((size_t)b*MAXP + p)*DD + o] = acc[p] + bias;
}

// ================= finalize bounds =========================================
__global__ void k_final(float* __restrict__ out, int out_size){
    if (threadIdx.x == 0 && blockIdx.x == 0){
        int f = g_first, l = g_last;
        float s0 = -1.f, s1 = -1.f;
        if (f != 0x7fffffff){
            s0 = (float)max(0, f - 2);
            s1 = (float)min(SS - 1, l + 2);
        }
        if (out_size >= BB*MAXP*DD + 2){
            out[BB*MAXP*DD + 0] = s0;
            out[BB*MAXP*DD + 1] = s1;
        }
    }
}

// ===========================================================================
extern "C" void kernel_launch(void* const* d_in, const int* in_sizes, int n_in,
                              void* d_out, int out_size) {
    const float* latent = (const float*)d_in[0];
    const int*   mask   = (const int*)  d_in[1];
    const float* proj_w = (const float*)d_in[2];
    const float* proj_b = (const float*)d_in[3];
    const float* w1     = (const float*)d_in[4];
    const float* b1     = (const float*)d_in[5];
    const float* w2     = (const float*)d_in[6];
    const float* b2     = (const float*)d_in[7];
    float* out = (float*)d_out;

    k_prep <<< (NKT*FF*16 + 255)/256, 256 >>>(w1);
    k_cos  <<< M_TOTAL/32, 256 >>>(latent);
    k_gemm <<< dim3(4, M_TOTAL/128), 256 >>>(b1, w2);
    k_score<<< M_TOTAL/256, 256 >>>(b2);
    k_rule <<< M_TOTAL/256, 256 >>>();
    k_pool <<< BB, 256 >>>(latent, mask);
    k_patch<<< dim3(DD/128, BB), 128 >>>(proj_w, proj_b, out);
    k_final<<< 1, 32 >>>(out, out_size);
}

// round 9
// speedup vs baseline: 1.4498x; 1.0739x over previous
#include <cuda_runtime.h>
#include <cuda_bf16.h>
#include <cuda_fp16.h>
#include <cuda_fp8.h>
#include <math.h>
#include <stdint.h>

#define BB 8
#define SS 4096
#define DD 1024
#define FF 512
#define M_TOTAL (BB*SS)   // 32768
#define MAXP 8
#define NKT 16            // 1024/64 k-tiles
#define W1SCALE 64.0f
#define W1INV   0.015625f

// ---------------- device scratch ----------------
// X as e4m3, tile-linear: [mtile 0..255][kt 0..15][row 0..127][64 B]
__device__ uint32_t g_Xq[(size_t)M_TOTAL * (DD/4)];      // 32 MB
// 64*W1 as e4m3, tile-linear: [kt 0..15][n 0..511][64 B]
__device__ uint32_t g_Bpk[NKT * FF * 16];                // 512 KB
__device__ float g_partial[M_TOTAL*8];
__device__ float g_scores[M_TOTAL];
__device__ float g_norm2[M_TOTAL];
__device__ float g_dot[M_TOTAL];
__device__ float g_pooled[BB*MAXP*DD];
__device__ int g_first, g_last;

// ---------------- helpers ----------------
__device__ __forceinline__ uint32_t s2u(const void* p){
    uint32_t a;
    asm("{ .reg .u64 t; cvta.to.shared.u64 t, %1; cvt.u32.u64 %0, t; }" : "=r"(a) : "l"(p));
    return a;
}
__device__ __forceinline__ void cp16(uint32_t dst, const void* src){
    asm volatile("cp.async.cg.shared.global [%0], [%1], 16;" :: "r"(dst), "l"(src) : "memory");
}
__device__ __forceinline__ void cp_commit(){ asm volatile("cp.async.commit_group;" ::: "memory"); }
__device__ __forceinline__ void cp_wait0(){ asm volatile("cp.async.wait_group 0;" ::: "memory"); }
__device__ __forceinline__ void cp_wait1(){ asm volatile("cp.async.wait_group 1;" ::: "memory"); }

// fp8 e4m3 m16n8k32 MMA, f16 accum (2 C/D regs = f16x2 pairs)
__device__ __forceinline__ void mmaqh(unsigned* d, const unsigned* a, unsigned b0, unsigned b1){
    asm volatile(
      "mma.sync.aligned.m16n8k32.row.col.f16.e4m3.e4m3.f16 "
      "{%0,%1}, {%2,%3,%4,%5}, {%6,%7}, {%0,%1};\n"
      : "+r"(d[0]), "+r"(d[1])
      : "r"(a[0]), "r"(a[1]), "r"(a[2]), "r"(a[3]), "r"(b0), "r"(b1));
}

// ldmatrix x4 (b16 tiles; bytes are dtype-agnostic)
__device__ __forceinline__ void ldsm4(unsigned* r, uint32_t addr){
    asm volatile("ldmatrix.sync.aligned.m8n8.x4.shared.b16 {%0,%1,%2,%3}, [%4];"
                 : "=r"(r[0]), "=r"(r[1]), "=r"(r[2]), "=r"(r[3]) : "r"(addr));
}

__device__ __forceinline__ uint32_t pack4_e4m3(float x, float y, float z, float w){
    __nv_fp8x2_storage_t p0 = __nv_cvt_float2_to_fp8x2(make_float2(x, y), __NV_SATFINITE, __NV_E4M3);
    __nv_fp8x2_storage_t p1 = __nv_cvt_float2_to_fp8x2(make_float2(z, w), __NV_SATFINITE, __NV_E4M3);
    return ((uint32_t)p1 << 16) | (uint32_t)p0;
}

// ================= prep: pack 64*W1 -> [kt][n][64B] e4m3 rows =============
__global__ void k_prep(const float* __restrict__ W1){
    int idx = blockIdx.x*256 + threadIdx.x;    // 131072 words
    if (idx == 0){ g_first = 0x7fffffff; g_last = -1; }
    if (idx >= NKT*FF*16) return;
    int kt = idx >> 13;          // 8192 words per ktile
    int wo = idx & 8191;
    int n  = wo >> 4;
    int ww = wo & 15;
    int k  = kt*64 + 4*ww;
    g_Bpk[idx] = pack4_e4m3(W1[(size_t)k*FF + n]     * W1SCALE,
                            W1[(size_t)(k+1)*FF + n] * W1SCALE,
                            W1[(size_t)(k+2)*FF + n] * W1SCALE,
                            W1[(size_t)(k+3)*FF + n] * W1SCALE);
}

// ===== k_cos: norms + adjacent dots + f32->e4m3 tile-linear conversion =====
__global__ __launch_bounds__(256) void k_cos(const float* __restrict__ X){
    int tid = threadIdx.x, w = tid>>5, lane = tid&31;
    int base = blockIdx.x*32 + w*4;
    const float4* xp = (const float4*)X;
    float4 a[8];
    size_t rb = (size_t)base*(DD/4);
    #pragma unroll
    for (int t = 0; t < 8; t++) a[t] = xp[rb + lane + t*32];
    #pragma unroll
    for (int j = 0; j < 4; j++){
        int s = base + j;
        // write e4m3 copy of row s (tile-linear)
        {
            int mtile = s >> 7, rl = s & 127;
            #pragma unroll
            for (int t = 0; t < 8; t++){
                int kt = (lane >> 4) + 2*t;            // col/64
                int wi = lane & 15;                    // word within 64B row
                uint32_t q = pack4_e4m3(a[t].x, a[t].y, a[t].z, a[t].w);
                size_t di = ((size_t)(mtile*NKT + kt)*128 + rl)*16 + wi;
                g_Xq[di] = q;
            }
        }
        float n2 = 0.f;
        #pragma unroll
        for (int t = 0; t < 8; t++)
            n2 += a[t].x*a[t].x + a[t].y*a[t].y + a[t].z*a[t].z + a[t].w*a[t].w;
        bool pv = ((s & (SS-1)) != (SS-1));
        float4 b[8];
        float dt = 0.f;
        if (pv){
            size_t rb2 = (size_t)(s+1)*(DD/4);
            #pragma unroll
            for (int t = 0; t < 8; t++){
                b[t] = xp[rb2 + lane + t*32];
                dt += a[t].x*b[t].x + a[t].y*b[t].y + a[t].z*b[t].z + a[t].w*b[t].w;
            }
        }
        #pragma unroll
        for (int o = 16; o > 0; o >>= 1){
            n2 += __shfl_xor_sync(0xffffffffu, n2, o);
            dt += __shfl_xor_sync(0xffffffffu, dt, o);
        }
        if (lane == 0){ g_norm2[s] = n2; if (pv) g_dot[s] = dt; }
        #pragma unroll
        for (int t = 0; t < 8; t++) a[t] = b[t];
    }
}

// ============ GEMM: double-buffered cp.async + fp8 QMMA (f16 acc) =========
// per CTA: 128 rows x 128 cols, k-tiles of 64 (e4m3). smem rows 64->80 B.
#define ROWB 80
__global__ __launch_bounds__(256) void k_gemm(const float* __restrict__ b1,
                                              const float* __restrict__ w2){
    __shared__ __align__(16) char As[2][128*ROWB];
    __shared__ __align__(16) char Bs[2][128*ROWB];
    __shared__ float b1s[FF], w2s[FF];

    const int nc  = blockIdx.x;          // 0..3
    const int mt0 = blockIdx.y;          // m-tile id (128 rows)
    const int m0  = mt0 * 128;
    const int n0  = nc * 128;
    const int tid = threadIdx.x;
    const int warp = tid >> 5, lane = tid & 31;
    const int warpM = warp >> 1, warpN = warp & 1;
    const int lr = lane >> 2, qc = lane & 3;

    #pragma unroll
    for (int j = 0; j < 2; j++){
        b1s[tid + j*256] = b1[tid + j*256];
        w2s[tid + j*256] = w2[tid + j*256];
    }

    const uint32_t as0 = s2u(As[0]), as1 = s2u(As[1]);
    const uint32_t bs0 = s2u(Bs[0]), bs1 = s2u(Bs[1]);

    // per-lane ldmatrix source offsets
    const int arow = warpM*32 + (lane & 7) + ((lane >> 3) & 1)*8;
    const int abyt = ((lane >> 4) & 1)*16;
    const int brow = warpN*64 + (lane & 7) + ((lane >> 4) & 1)*8;
    const int bbyt = ((lane >> 3) & 1)*16;
    const uint32_t aoff = (uint32_t)(arow*ROWB + abyt);
    const uint32_t boff = (uint32_t)(brow*ROWB + bbyt);

    const char* xsrc = (const char*)g_Xq + (size_t)mt0 * (NKT*128*64);
    const char* bsrc = (const char*)g_Bpk;

    auto stage = [&](int kt, int buf){
        uint32_t ad = buf ? as1 : as0;
        uint32_t bd = buf ? bs1 : bs0;
        const char* xs = xsrc + (size_t)kt*(128*64);
        const char* bs = bsrc + ((size_t)kt*512 + n0)*64;
        #pragma unroll
        for (int i = 0; i < 2; i++){
            int g = tid + i*256;
            int row = g >> 2, cb = (g & 3)*16;
            cp16(ad + row*ROWB + cb, xs + row*64 + cb);
        }
        #pragma unroll
        for (int i = 0; i < 2; i++){
            int g = tid + i*256;
            int row = g >> 2, cb = (g & 3)*16;
            cp16(bd + row*ROWB + cb, bs + row*64 + cb);
        }
    };

    unsigned int acc[2][8][2];
    #pragma unroll
    for (int mt=0; mt<2; mt++)
      #pragma unroll
      for (int nt=0; nt<8; nt++){
        acc[mt][nt][0] = 0u; acc[mt][nt][1] = 0u;
      }

    stage(0, 0);
    cp_commit();

    for (int kt = 0; kt < NKT; kt++){
        int cur = kt & 1;
        if (kt + 1 < NKT){
            stage(kt + 1, cur ^ 1);
            cp_commit();
            cp_wait1();
        } else {
            cp_wait0();
        }
        __syncthreads();
        const uint32_t aA = (cur ? as1 : as0) + aoff;
        const uint32_t bA = (cur ? bs1 : bs0) + boff;
        #pragma unroll
        for (int ks = 0; ks < 2; ks++){   // two k32 windows within 64B row
            unsigned int a[2][4];
            ldsm4(a[0], aA + ks*32);               // rows +0..15
            ldsm4(a[1], aA + 16*ROWB + ks*32);     // rows +16..31
            unsigned int b[8][2];
            #pragma unroll
            for (int ntp = 0; ntp < 4; ntp++){
                unsigned int r[4];
                ldsm4(r, bA + ntp*16*ROWB + ks*32);
                b[2*ntp  ][0] = r[0]; b[2*ntp  ][1] = r[1];
                b[2*ntp+1][0] = r[2]; b[2*ntp+1][1] = r[3];
            }
            #pragma unroll
            for (int nt = 0; nt < 8; nt++){
                mmaqh(acc[0][nt], a[0], b[nt][0], b[nt][1]);
                mmaqh(acc[1][nt], a[1], b[nt][0], b[nt][1]);
            }
        }
        __syncthreads();
    }

    // epilogue: per-row partial of relu(acc/64 + b1)*w2 over this CTA's 128 cols
    float b1r[16], w2r[16];
    #pragma unroll
    for (int nt = 0; nt < 8; nt++){
        #pragma unroll
        for (int e = 0; e < 2; e++){
            int n = n0 + warpN*64 + nt*8 + qc*2 + e;
            b1r[nt*2+e] = b1s[n];
            w2r[nt*2+e] = w2s[n];
        }
    }
    #pragma unroll
    for (int mt = 0; mt < 2; mt++){
        float sA = 0.f, sB = 0.f;
        #pragma unroll
        for (int nt = 0; nt < 8; nt++){
            float2 vA = __half22float2(*(__half2*)&acc[mt][nt][0]);  // row lr,   cols qc*2, qc*2+1
            float2 vB = __half22float2(*(__half2*)&acc[mt][nt][1]);  // row lr+8, cols qc*2, qc*2+1
            sA += fmaxf(vA.x * W1INV + b1r[nt*2+0], 0.f) * w2r[nt*2+0];
            sA += fmaxf(vA.y * W1INV + b1r[nt*2+1], 0.f) * w2r[nt*2+1];
            sB += fmaxf(vB.x * W1INV + b1r[nt*2+0], 0.f) * w2r[nt*2+0];
            sB += fmaxf(vB.y * W1INV + b1r[nt*2+1], 0.f) * w2r[nt*2+1];
        }
        sA += __shfl_xor_sync(0xffffffffu, sA, 1);
        sA += __shfl_xor_sync(0xffffffffu, sA, 2);
        sB += __shfl_xor_sync(0xffffffffu, sB, 1);
        sB += __shfl_xor_sync(0xffffffffu, sB, 2);
        if (qc == 0){
            int rA = m0 + warpM*32 + mt*16 + lr;
            g_partial[(size_t)rA*8     + nc*2 + warpN] = sA;
            g_partial[(size_t)(rA+8)*8 + nc*2 + warpN] = sB;
        }
    }
}

// ================= scores: sigmoid(b2 + sum partials) ======================
__global__ void k_score(const float* __restrict__ b2){
    int i = blockIdx.x*256 + threadIdx.x;
    if (i < M_TOTAL){
        float l = b2[0];
        #pragma unroll
        for (int j = 0; j < 8; j++) l += g_partial[(size_t)i*8 + j];
        g_scores[i] = 1.f / (1.f + expf(-l));
    }
}

// ================= EOS rules + global bounds ===============================
__global__ void k_rule(){
    int i = blockIdx.x*256 + threadIdx.x;
    if (i >= M_TOTAL) return;
    int t = i & (SS-1);
    if (t < 2) return;
    float sc = g_scores[i];
    bool run = (sc > 0.7f) && (g_scores[i-1] > 0.7f) && (g_scores[i-2] > 0.7f);
    float na = fmaxf(sqrtf(g_norm2[i-1]), 1e-8f);
    float nb = fmaxf(sqrtf(g_norm2[i]),   1e-8f);
    float cosv = g_dot[i-1] / (na * nb);
    bool cr = (cosv < 0.3f) && (sc > 0.5f);
    if (run || cr){
        atomicMin(&g_first, t);
        atomicMax(&g_last,  t);
    }
}

// ================= segment pooling (early-exit prefix scan) ================
__global__ void k_pool(const float* __restrict__ X, const int* __restrict__ Mk){
    __shared__ float ssum[MAXP*DD];
    __shared__ int   scnt[MAXP];
    int b = blockIdx.x;
    int tid = threadIdx.x;            // 256
    for (int i = tid; i < MAXP*DD; i += 256) ssum[i] = 0.f;
    if (tid < MAXP) scnt[tid] = 0;
    __syncthreads();
    const float* xb = X + (size_t)b*SS*DD;
    const int*   mb = Mk + (size_t)b*SS;
    int c = 0;
    for (int s = 0; s < SS && c < MAXP; s++){
        #pragma unroll
        for (int j = 0; j < 4; j++){
            int d = tid + j*256;
            ssum[c*DD + d] += xb[(size_t)s*DD + d];
        }
        if (tid == 0) scnt[c]++;
        c += (mb[s] != 0) ? 1 : 0;
    }
    __syncthreads();
    #pragma unroll
    for (int p = 0; p < MAXP; p++){
        float inv = 1.f / (float)max(scnt[p], 1);
        #pragma unroll
        for (int j = 0; j < 4; j++){
            int d = tid + j*256;
            g_pooled[((size_t)b*MAXP + p)*DD + d] = ssum[p*DD + d] * inv;
        }
    }
}

// ================= patches = pooled @ proj_w + proj_b ======================
__global__ void k_patch(const float* __restrict__ Pw, const float* __restrict__ Pb,
                        float* __restrict__ out){
    __shared__ float ps[MAXP*DD];
    int oc = blockIdx.x, b = blockIdx.y;
    int tid = threadIdx.x;            // 128
    for (int i = tid; i < MAXP*DD; i += 128) ps[i] = g_pooled[(size_t)b*MAXP*DD + i];
    __syncthreads();
    int o = oc*128 + tid;
    float acc[MAXP];
    #pragma unroll
    for (int p = 0; p < MAXP; p++) acc[p] = 0.f;
    for (int d = 0; d < DD; d++){
        float w = Pw[(size_t)d*DD + o];
        #pragma unroll
        for (int p = 0; p < MAXP; p++) acc[p] += ps[p*DD + d] * w;
    }
    float bias = Pb[o];
    #pragma unroll
    for (int p = 0; p < MAXP; p++)
        out[((size_t)b*MAXP + p)*DD + o] = acc[p] + bias;
}

// ================= finalize bounds =========================================
__global__ void k_final(float* __restrict__ out, int out_size){
    if (threadIdx.x == 0 && blockIdx.x == 0){
        int f = g_first, l = g_last;
        float s0 = -1.f, s1 = -1.f;
        if (f != 0x7fffffff){
            s0 = (float)max(0, f - 2);
            s1 = (float)min(SS - 1, l + 2);
        }
        if (out_size >= BB*MAXP*DD + 2){
            out[BB*MAXP*DD + 0] = s0;
            out[BB*MAXP*DD + 1] = s1;
        }
    }
}

// ===========================================================================
extern "C" void kernel_launch(void* const* d_in, const int* in_sizes, int n_in,
                              void* d_out, int out_size) {
    const float* latent = (const float*)d_in[0];
    const int*   mask   = (const int*)  d_in[1];
    const float* proj_w = (const float*)d_in[2];
    const float* proj_b = (const float*)d_in[3];
    const float* w1     = (const float*)d_in[4];
    const float* b1     = (const float*)d_in[5];
    const float* w2     = (const float*)d_in[6];
    const float* b2     = (const float*)d_in[7];
    float* out = (float*)d_out;

    k_prep <<< (NKT*FF*16 + 255)/256, 256 >>>(w1);
    k_cos  <<< M_TOTAL/32, 256 >>>(latent);
    k_gemm <<< dim3(4, M_TOTAL/128), 256 >>>(b1, w2);
    k_score<<< M_TOTAL/256, 256 >>>(b2);
    k_rule <<< M_TOTAL/256, 256 >>>();
    k_pool <<< BB, 256 >>>(latent, mask);
    k_patch<<< dim3(DD/128, BB), 128 >>>(proj_w, proj_b, out);
    k_final<<< 1, 32 >>>(out, out_size);
}

// round 10
// speedup vs baseline: 1.5144x; 1.0446x over previous
#include <cuda_runtime.h>
#include <cuda_bf16.h>
#include <cuda_fp16.h>
#include <cuda_fp8.h>
#include <math.h>
#include <stdint.h>

#define BB 8
#define SS 4096
#define DD 1024
#define FF 512
#define M_TOTAL (BB*SS)   // 32768
#define MAXP 8
#define NKT 16            // 1024/64 k-tiles
#define W1SCALE 64.0f
#define W1INV   0.015625f

// ---------------- device scratch ----------------
__device__ uint32_t g_Xq[(size_t)M_TOTAL * (DD/4)];      // 32 MB e4m3 tile-linear
__device__ uint32_t g_Bpk[NKT * FF * 16];                // 512 KB e4m3 tile-linear
__device__ float g_partial[M_TOTAL*8];
__device__ float g_norm2[M_TOTAL];
__device__ float g_dot[M_TOTAL];
__device__ float g_pooled[BB*MAXP*DD];
__device__ int g_first, g_last;

// ---------------- helpers ----------------
__device__ __forceinline__ uint32_t s2u(const void* p){
    uint32_t a;
    asm("{ .reg .u64 t; cvta.to.shared.u64 t, %1; cvt.u32.u64 %0, t; }" : "=r"(a) : "l"(p));
    return a;
}
__device__ __forceinline__ void cp16(uint32_t dst, const void* src){
    asm volatile("cp.async.cg.shared.global [%0], [%1], 16;" :: "r"(dst), "l"(src) : "memory");
}
__device__ __forceinline__ void cp_commit(){ asm volatile("cp.async.commit_group;" ::: "memory"); }
__device__ __forceinline__ void cp_wait0(){ asm volatile("cp.async.wait_group 0;" ::: "memory"); }
__device__ __forceinline__ void cp_wait2(){ asm volatile("cp.async.wait_group 2;" ::: "memory"); }

// fp8 e4m3 m16n8k32 MMA, f16 accum
__device__ __forceinline__ void mmaqh(unsigned* d, const unsigned* a, unsigned b0, unsigned b1){
    asm volatile(
      "mma.sync.aligned.m16n8k32.row.col.f16.e4m3.e4m3.f16 "
      "{%0,%1}, {%2,%3,%4,%5}, {%6,%7}, {%0,%1};\n"
      : "+r"(d[0]), "+r"(d[1])
      : "r"(a[0]), "r"(a[1]), "r"(a[2]), "r"(a[3]), "r"(b0), "r"(b1));
}
__device__ __forceinline__ void ldsm4(unsigned* r, uint32_t addr){
    asm volatile("ldmatrix.sync.aligned.m8n8.x4.shared.b16 {%0,%1,%2,%3}, [%4];"
                 : "=r"(r[0]), "=r"(r[1]), "=r"(r[2]), "=r"(r[3]) : "r"(addr));
}
__device__ __forceinline__ uint32_t pack4_e4m3(float x, float y, float z, float w){
    __nv_fp8x2_storage_t p0 = __nv_cvt_float2_to_fp8x2(make_float2(x, y), __NV_SATFINITE, __NV_E4M3);
    __nv_fp8x2_storage_t p1 = __nv_cvt_float2_to_fp8x2(make_float2(z, w), __NV_SATFINITE, __NV_E4M3);
    return ((uint32_t)p1 << 16) | (uint32_t)p0;
}

// ================= init: reset bounds ======================================
__global__ void k_init(){
    g_first = 0x7fffffff; g_last = -1;
}

// ================= prep: pack 64*W1 -> [kt][n][64B] e4m3 rows ==============
__global__ void k_prep(const float* __restrict__ W1){
    int idx = blockIdx.x*256 + threadIdx.x;    // 131072 words
    if (idx >= NKT*FF*16) return;
    int kt = idx >> 13;
    int wo = idx & 8191;
    int n  = wo >> 4;
    int ww = wo & 15;
    int k  = kt*64 + 4*ww;
    g_Bpk[idx] = pack4_e4m3(W1[(size_t)k*FF + n]     * W1SCALE,
                            W1[(size_t)(k+1)*FF + n] * W1SCALE,
                            W1[(size_t)(k+2)*FF + n] * W1SCALE,
                            W1[(size_t)(k+3)*FF + n] * W1SCALE);
}

// ===== k_cos: norms + adjacent dots + f32->e4m3 tile-linear conversion =====
__global__ __launch_bounds__(256) void k_cos(const float* __restrict__ X){
    int tid = threadIdx.x, w = tid>>5, lane = tid&31;
    int base = blockIdx.x*32 + w*4;
    const float4* xp = (const float4*)X;
    float4 a[8];
    size_t rb = (size_t)base*(DD/4);
    #pragma unroll
    for (int t = 0; t < 8; t++) a[t] = xp[rb + lane + t*32];
    #pragma unroll
    for (int j = 0; j < 4; j++){
        int s = base + j;
        {
            int mtile = s >> 7, rl = s & 127;
            #pragma unroll
            for (int t = 0; t < 8; t++){
                int kt = (lane >> 4) + 2*t;
                int wi = lane & 15;
                uint32_t q = pack4_e4m3(a[t].x, a[t].y, a[t].z, a[t].w);
                size_t di = ((size_t)(mtile*NKT + kt)*128 + rl)*16 + wi;
                g_Xq[di] = q;
            }
        }
        float n2 = 0.f;
        #pragma unroll
        for (int t = 0; t < 8; t++)
            n2 += a[t].x*a[t].x + a[t].y*a[t].y + a[t].z*a[t].z + a[t].w*a[t].w;
        bool pv = ((s & (SS-1)) != (SS-1));
        float4 b[8];
        float dt = 0.f;
        if (pv){
            size_t rb2 = (size_t)(s+1)*(DD/4);
            #pragma unroll
            for (int t = 0; t < 8; t++){
                b[t] = xp[rb2 + lane + t*32];
                dt += a[t].x*b[t].x + a[t].y*b[t].y + a[t].z*b[t].z + a[t].w*b[t].w;
            }
        }
        #pragma unroll
        for (int o = 16; o > 0; o >>= 1){
            n2 += __shfl_xor_sync(0xffffffffu, n2, o);
            dt += __shfl_xor_sync(0xffffffffu, dt, o);
        }
        if (lane == 0){ g_norm2[s] = n2; if (pv) g_dot[s] = dt; }
        #pragma unroll
        for (int t = 0; t < 8; t++) a[t] = b[t];
    }
}

// ===== GEMM: 4-buffer cp.async pipeline (1 sync/ktile) + fp8 QMMA f16acc ===
#define ROWB 80
#define TILEB (128*ROWB)          // 10240 B per tile buffer
#define SM_B1OFF (8*TILEB)        // 81920
#define SM_W2OFF (SM_B1OFF + 2048)
#define SM_DYN   (SM_W2OFF + 2048)  // 86016
__global__ __launch_bounds__(256) void k_gemm(const float* __restrict__ b1,
                                              const float* __restrict__ w2){
    extern __shared__ __align__(16) char dsm[];
    char* Abuf[4]; char* Bbuf[4];
    #pragma unroll
    for (int b = 0; b < 4; b++){
        Abuf[b] = dsm + b*TILEB;
        Bbuf[b] = dsm + 4*TILEB + b*TILEB;
    }
    float* b1s = (float*)(dsm + SM_B1OFF);
    float* w2s = (float*)(dsm + SM_W2OFF);

    const int nc  = blockIdx.x;          // 0..3
    const int mt0 = blockIdx.y;
    const int m0  = mt0 * 128;
    const int n0  = nc * 128;
    const int tid = threadIdx.x;
    const int warp = tid >> 5, lane = tid & 31;
    const int warpM = warp >> 1, warpN = warp & 1;
    const int lr = lane >> 2, qc = lane & 3;

    #pragma unroll
    for (int j = 0; j < 2; j++){
        b1s[tid + j*256] = b1[tid + j*256];
        w2s[tid + j*256] = w2[tid + j*256];
    }

    const int arow = warpM*32 + (lane & 7) + ((lane >> 3) & 1)*8;
    const int abyt = ((lane >> 4) & 1)*16;
    const int brow = warpN*64 + (lane & 7) + ((lane >> 4) & 1)*8;
    const int bbyt = ((lane >> 3) & 1)*16;
    const uint32_t aoff = (uint32_t)(arow*ROWB + abyt);
    const uint32_t boff = (uint32_t)(brow*ROWB + bbyt);

    const char* xsrc = (const char*)g_Xq + (size_t)mt0 * (NKT*128*64);
    const char* bsrc = (const char*)g_Bpk;

    auto stage = [&](int kt, int buf){
        uint32_t ad = s2u(Abuf[buf]);
        uint32_t bd = s2u(Bbuf[buf]);
        const char* xs = xsrc + (size_t)kt*(128*64);
        const char* bs = bsrc + ((size_t)kt*512 + n0)*64;
        #pragma unroll
        for (int i = 0; i < 2; i++){
            int g = tid + i*256;
            int row = g >> 2, cb = (g & 3)*16;
            cp16(ad + row*ROWB + cb, xs + row*64 + cb);
        }
        #pragma unroll
        for (int i = 0; i < 2; i++){
            int g = tid + i*256;
            int row = g >> 2, cb = (g & 3)*16;
            cp16(bd + row*ROWB + cb, bs + row*64 + cb);
        }
    };

    unsigned int acc[2][8][2];
    #pragma unroll
    for (int mt=0; mt<2; mt++)
      #pragma unroll
      for (int nt=0; nt<8; nt++){ acc[mt][nt][0] = 0u; acc[mt][nt][1] = 0u; }

    stage(0, 0); cp_commit();
    stage(1, 1); cp_commit();

    for (int kt = 0; kt < NKT; kt++){
        int buf = kt & 3;
        if (kt + 2 < NKT){
            stage(kt + 2, (kt + 2) & 3);
            cp_commit();
            cp_wait2();               // group kt complete (kt+1, kt+2 may fly)
        } else {
            cp_wait0();
        }
        __syncthreads();              // publish group kt to all warps;
                                      // also fences laggards off buffer (kt+2)&3
        const uint32_t aA = s2u(Abuf[buf]) + aoff;
        const uint32_t bA = s2u(Bbuf[buf]) + boff;
        #pragma unroll
        for (int ks = 0; ks < 2; ks++){
            unsigned int a[2][4];
            ldsm4(a[0], aA + ks*32);
            ldsm4(a[1], aA + 16*ROWB + ks*32);
            unsigned int b[8][2];
            #pragma unroll
            for (int ntp = 0; ntp < 4; ntp++){
                unsigned int r[4];
                ldsm4(r, bA + ntp*16*ROWB + ks*32);
                b[2*ntp  ][0] = r[0]; b[2*ntp  ][1] = r[1];
                b[2*ntp+1][0] = r[2]; b[2*ntp+1][1] = r[3];
            }
            #pragma unroll
            for (int nt = 0; nt < 8; nt++){
                mmaqh(acc[0][nt], a[0], b[nt][0], b[nt][1]);
                mmaqh(acc[1][nt], a[1], b[nt][0], b[nt][1]);
            }
        }
    }

    // epilogue: per-row partial of relu(acc/64 + b1)*w2 over this CTA's 128 cols
    float b1r[16], w2r[16];
    #pragma unroll
    for (int nt = 0; nt < 8; nt++){
        #pragma unroll
        for (int e = 0; e < 2; e++){
            int n = n0 + warpN*64 + nt*8 + qc*2 + e;
            b1r[nt*2+e] = b1s[n];
            w2r[nt*2+e] = w2s[n];
        }
    }
    #pragma unroll
    for (int mt = 0; mt < 2; mt++){
        float sA = 0.f, sB = 0.f;
        #pragma unroll
        for (int nt = 0; nt < 8; nt++){
            float2 vA = __half22float2(*(__half2*)&acc[mt][nt][0]);
            float2 vB = __half22float2(*(__half2*)&acc[mt][nt][1]);
            sA += fmaxf(vA.x * W1INV + b1r[nt*2+0], 0.f) * w2r[nt*2+0];
            sA += fmaxf(vA.y * W1INV + b1r[nt*2+1], 0.f) * w2r[nt*2+1];
            sB += fmaxf(vB.x * W1INV + b1r[nt*2+0], 0.f) * w2r[nt*2+0];
            sB += fmaxf(vB.y * W1INV + b1r[nt*2+1], 0.f) * w2r[nt*2+1];
        }
        sA += __shfl_xor_sync(0xffffffffu, sA, 1);
        sA += __shfl_xor_sync(0xffffffffu, sA, 2);
        sB += __shfl_xor_sync(0xffffffffu, sB, 1);
        sB += __shfl_xor_sync(0xffffffffu, sB, 2);
        if (qc == 0){
            int rA = m0 + warpM*32 + mt*16 + lr;
            g_partial[(size_t)rA*8     + nc*2 + warpN] = sA;
            g_partial[(size_t)(rA+8)*8 + nc*2 + warpN] = sB;
        }
    }
}

// ============ rules: fused score (smem halo) + EOS bounds ==================
__global__ __launch_bounds__(256) void k_rule(const float* __restrict__ b2){
    __shared__ float sc[258];
    int base = blockIdx.x*256;
    int tid = threadIdx.x;
    int i = base + tid;
    float bb = __ldg(b2);
    {
        float l = bb;
        #pragma unroll
        for (int j = 0; j < 8; j++) l += g_partial[(size_t)i*8 + j];
        sc[tid + 2] = 1.f / (1.f + expf(-l));
    }
    if (tid < 2){
        int r = base - 2 + tid;
        float v = 0.f;
        if (r >= 0){
            float l = bb;
            #pragma unroll
            for (int j = 0; j < 8; j++) l += g_partial[(size_t)r*8 + j];
            v = 1.f / (1.f + expf(-l));
        }
        sc[tid] = v;
    }
    __syncthreads();
    int t = i & (SS-1);
    if (t < 2) return;
    float s0 = sc[tid+2], s1 = sc[tid+1], s2 = sc[tid];
    bool run = (s0 > 0.7f) && (s1 > 0.7f) && (s2 > 0.7f);
    float na = fmaxf(sqrtf(g_norm2[i-1]), 1e-8f);
    float nb = fmaxf(sqrtf(g_norm2[i]),   1e-8f);
    float cosv = g_dot[i-1] / (na * nb);
    bool cr = (cosv < 0.3f) && (s0 > 0.5f);
    if (run || cr){
        atomicMin(&g_first, t);
        atomicMax(&g_last,  t);
    }
}

// ================= segment pooling (early-exit prefix scan) ================
__global__ void k_pool(const float* __restrict__ X, const int* __restrict__ Mk){
    __shared__ float ssum[MAXP*DD];
    __shared__ int   scnt[MAXP];
    int b = blockIdx.x;
    int tid = threadIdx.x;
    for (int i = tid; i < MAXP*DD; i += 256) ssum[i] = 0.f;
    if (tid < MAXP) scnt[tid] = 0;
    __syncthreads();
    const float* xb = X + (size_t)b*SS*DD;
    const int*   mb = Mk + (size_t)b*SS;
    int c = 0;
    for (int s = 0; s < SS && c < MAXP; s++){
        #pragma unroll
        for (int j = 0; j < 4; j++){
            int d = tid + j*256;
            ssum[c*DD + d] += xb[(size_t)s*DD + d];
        }
        if (tid == 0) scnt[c]++;
        c += (mb[s] != 0) ? 1 : 0;
    }
    __syncthreads();
    #pragma unroll
    for (int p = 0; p < MAXP; p++){
        float inv = 1.f / (float)max(scnt[p], 1);
        #pragma unroll
        for (int j = 0; j < 4; j++){
            int d = tid + j*256;
            g_pooled[((size_t)b*MAXP + p)*DD + d] = ssum[p*DD + d] * inv;
        }
    }
}

// ================= patches = pooled @ proj_w + proj_b ======================
__global__ void k_patch(const float* __restrict__ Pw, const float* __restrict__ Pb,
                        float* __restrict__ out){
    __shared__ float ps[MAXP*DD];
    int oc = blockIdx.x, b = blockIdx.y;
    int tid = threadIdx.x;
    for (int i = tid; i < MAXP*DD; i += 128) ps[i] = g_pooled[(size_t)b*MAXP*DD + i];
    __syncthreads();
    int o = oc*128 + tid;
    float acc[MAXP];
    #pragma unroll
    for (int p = 0; p < MAXP; p++) acc[p] = 0.f;
    for (int d = 0; d < DD; d++){
        float w = Pw[(size_t)d*DD + o];
        #pragma unroll
        for (int p = 0; p < MAXP; p++) acc[p] += ps[p*DD + d] * w;
    }
    float bias = Pb[o];
    #pragma unroll
    for (int p = 0; p < MAXP; p++)
        out[((size_t)b*MAXP + p)*DD + o] = acc[p] + bias;
}

// ================= finalize bounds =========================================
__global__ void k_final(float* __restrict__ out, int out_size){
    if (threadIdx.x == 0 && blockIdx.x == 0){
        int f = g_first, l = g_last;
        float s0 = -1.f, s1 = -1.f;
        if (f != 0x7fffffff){
            s0 = (float)max(0, f - 2);
            s1 = (float)min(SS - 1, l + 2);
        }
        if (out_size >= BB*MAXP*DD + 2){
            out[BB*MAXP*DD + 0] = s0;
            out[BB*MAXP*DD + 1] = s1;
        }
    }
}

// ===========================================================================
extern "C" void kernel_launch(void* const* d_in, const int* in_sizes, int n_in,
                              void* d_out, int out_size) {
    const float* latent = (const float*)d_in[0];
    const int*   mask   = (const int*)  d_in[1];
    const float* proj_w = (const float*)d_in[2];
    const float* proj_b = (const float*)d_in[3];
    const float* w1     = (const float*)d_in[4];
    const float* b1     = (const float*)d_in[5];
    const float* w2     = (const float*)d_in[6];
    const float* b2     = (const float*)d_in[7];
    float* out = (float*)d_out;

    cudaFuncSetAttribute(k_gemm, cudaFuncAttributeMaxDynamicSharedMemorySize, SM_DYN);

    // launch order chosen so ncu (-s 5 -c 1) profiles k_gemm (6th launch)
    k_init <<< 1, 1 >>>();
    k_prep <<< (NKT*FF*16 + 255)/256, 256 >>>(w1);
    k_pool <<< BB, 256 >>>(latent, mask);
    k_patch<<< dim3(DD/128, BB), 128 >>>(proj_w, proj_b, out);
    k_cos  <<< M_TOTAL/32, 256 >>>(latent);
    k_gemm <<< dim3(4, M_TOTAL/128), 256, SM_DYN >>>(b1, w2);
    k_rule <<< M_TOTAL/256, 256 >>>(b2);
    k_final<<< 1, 32 >>>(out, out_size);
}

// round 11
// speedup vs baseline: 2.6324x; 1.7382x over previous
#include <cuda_runtime.h>
#include <cuda_bf16.h>
#include <cuda_fp16.h>
#include <cuda_fp8.h>
#include <math.h>
#include <stdint.h>

#define BB 8
#define SS 4096
#define DD 1024
#define FF 512
#define M_TOTAL (BB*SS)   // 32768
#define MAXP 8
#define NKT 16            // 1024/64 k-tiles
#define KSP 8             // split-k factor for patch GEMM
#define W1SCALE 64.0f
#define W1INV   0.015625f

// ---------------- device scratch ----------------
__device__ uint32_t g_Xq[(size_t)M_TOTAL * (DD/4)];      // 32 MB e4m3 tile-linear
__device__ uint32_t g_Bpk[NKT * FF * 16];                // 512 KB e4m3 tile-linear
__device__ float g_partial[M_TOTAL*8];
__device__ float g_norm2[M_TOTAL];
__device__ float g_dot[M_TOTAL];
__device__ float g_pooled[BB*MAXP*DD];
__device__ float g_ppart[KSP*BB*MAXP*DD];                // 2 MB split-k partials
__device__ int g_first, g_last;

// ---------------- helpers ----------------
__device__ __forceinline__ uint32_t s2u(const void* p){
    uint32_t a;
    asm("{ .reg .u64 t; cvta.to.shared.u64 t, %1; cvt.u32.u64 %0, t; }" : "=r"(a) : "l"(p));
    return a;
}
__device__ __forceinline__ void cp16(uint32_t dst, const void* src){
    asm volatile("cp.async.cg.shared.global [%0], [%1], 16;" :: "r"(dst), "l"(src) : "memory");
}
__device__ __forceinline__ void cp_commit(){ asm volatile("cp.async.commit_group;" ::: "memory"); }
__device__ __forceinline__ void cp_wait0(){ asm volatile("cp.async.wait_group 0;" ::: "memory"); }
__device__ __forceinline__ void cp_wait2(){ asm volatile("cp.async.wait_group 2;" ::: "memory"); }

// fp8 e4m3 m16n8k32 MMA, f16 accum
__device__ __forceinline__ void mmaqh(unsigned* d, const unsigned* a, unsigned b0, unsigned b1){
    asm volatile(
      "mma.sync.aligned.m16n8k32.row.col.f16.e4m3.e4m3.f16 "
      "{%0,%1}, {%2,%3,%4,%5}, {%6,%7}, {%0,%1};\n"
      : "+r"(d[0]), "+r"(d[1])
      : "r"(a[0]), "r"(a[1]), "r"(a[2]), "r"(a[3]), "r"(b0), "r"(b1));
}
__device__ __forceinline__ void ldsm4(unsigned* r, uint32_t addr){
    asm volatile("ldmatrix.sync.aligned.m8n8.x4.shared.b16 {%0,%1,%2,%3}, [%4];"
                 : "=r"(r[0]), "=r"(r[1]), "=r"(r[2]), "=r"(r[3]) : "r"(addr));
}
__device__ __forceinline__ uint32_t pack4_e4m3(float x, float y, float z, float w){
    __nv_fp8x2_storage_t p0 = __nv_cvt_float2_to_fp8x2(make_float2(x, y), __NV_SATFINITE, __NV_E4M3);
    __nv_fp8x2_storage_t p1 = __nv_cvt_float2_to_fp8x2(make_float2(z, w), __NV_SATFINITE, __NV_E4M3);
    return ((uint32_t)p1 << 16) | (uint32_t)p0;
}

// ================= init: reset bounds ======================================
__global__ void k_init(){
    g_first = 0x7fffffff; g_last = -1;
}

// ================= prep: pack 64*W1 -> [kt][n][64B] e4m3 rows ==============
__global__ void k_prep(const float* __restrict__ W1){
    int idx = blockIdx.x*256 + threadIdx.x;    // 131072 words
    if (idx >= NKT*FF*16) return;
    int kt = idx >> 13;
    int wo = idx & 8191;
    int n  = wo >> 4;
    int ww = wo & 15;
    int k  = kt*64 + 4*ww;
    g_Bpk[idx] = pack4_e4m3(W1[(size_t)k*FF + n]     * W1SCALE,
                            W1[(size_t)(k+1)*FF + n] * W1SCALE,
                            W1[(size_t)(k+2)*FF + n] * W1SCALE,
                            W1[(size_t)(k+3)*FF + n] * W1SCALE);
}

// ===== k_cos: norms + adjacent dots + f32->e4m3 tile-linear conversion =====
__global__ __launch_bounds__(256) void k_cos(const float* __restrict__ X){
    int tid = threadIdx.x, w = tid>>5, lane = tid&31;
    int base = blockIdx.x*32 + w*4;
    const float4* xp = (const float4*)X;
    float4 a[8];
    size_t rb = (size_t)base*(DD/4);
    #pragma unroll
    for (int t = 0; t < 8; t++) a[t] = xp[rb + lane + t*32];
    #pragma unroll
    for (int j = 0; j < 4; j++){
        int s = base + j;
        {
            int mtile = s >> 7, rl = s & 127;
            #pragma unroll
            for (int t = 0; t < 8; t++){
                int kt = (lane >> 4) + 2*t;
                int wi = lane & 15;
                uint32_t q = pack4_e4m3(a[t].x, a[t].y, a[t].z, a[t].w);
                size_t di = ((size_t)(mtile*NKT + kt)*128 + rl)*16 + wi;
                g_Xq[di] = q;
            }
        }
        float n2 = 0.f;
        #pragma unroll
        for (int t = 0; t < 8; t++)
            n2 += a[t].x*a[t].x + a[t].y*a[t].y + a[t].z*a[t].z + a[t].w*a[t].w;
        bool pv = ((s & (SS-1)) != (SS-1));
        float4 b[8];
        float dt = 0.f;
        if (pv){
            size_t rb2 = (size_t)(s+1)*(DD/4);
            #pragma unroll
            for (int t = 0; t < 8; t++){
                b[t] = xp[rb2 + lane + t*32];
                dt += a[t].x*b[t].x + a[t].y*b[t].y + a[t].z*b[t].z + a[t].w*b[t].w;
            }
        }
        #pragma unroll
        for (int o = 16; o > 0; o >>= 1){
            n2 += __shfl_xor_sync(0xffffffffu, n2, o);
            dt += __shfl_xor_sync(0xffffffffu, dt, o);
        }
        if (lane == 0){ g_norm2[s] = n2; if (pv) g_dot[s] = dt; }
        #pragma unroll
        for (int t = 0; t < 8; t++) a[t] = b[t];
    }
}

// ===== GEMM: 4-buffer cp.async pipeline (1 sync/ktile) + fp8 QMMA f16acc ===
#define ROWB 80
#define TILEB (128*ROWB)
#define SM_B1OFF (8*TILEB)
#define SM_W2OFF (SM_B1OFF + 2048)
#define SM_DYN   (SM_W2OFF + 2048)
__global__ __launch_bounds__(256) void k_gemm(const float* __restrict__ b1,
                                              const float* __restrict__ w2){
    extern __shared__ __align__(16) char dsm[];
    char* Abuf[4]; char* Bbuf[4];
    #pragma unroll
    for (int b = 0; b < 4; b++){
        Abuf[b] = dsm + b*TILEB;
        Bbuf[b] = dsm + 4*TILEB + b*TILEB;
    }
    float* b1s = (float*)(dsm + SM_B1OFF);
    float* w2s = (float*)(dsm + SM_W2OFF);

    const int nc  = blockIdx.x;
    const int mt0 = blockIdx.y;
    const int m0  = mt0 * 128;
    const int n0  = nc * 128;
    const int tid = threadIdx.x;
    const int warp = tid >> 5, lane = tid & 31;
    const int warpM = warp >> 1, warpN = warp & 1;
    const int lr = lane >> 2, qc = lane & 3;

    #pragma unroll
    for (int j = 0; j < 2; j++){
        b1s[tid + j*256] = b1[tid + j*256];
        w2s[tid + j*256] = w2[tid + j*256];
    }

    const int arow = warpM*32 + (lane & 7) + ((lane >> 3) & 1)*8;
    const int abyt = ((lane >> 4) & 1)*16;
    const int brow = warpN*64 + (lane & 7) + ((lane >> 4) & 1)*8;
    const int bbyt = ((lane >> 3) & 1)*16;
    const uint32_t aoff = (uint32_t)(arow*ROWB + abyt);
    const uint32_t boff = (uint32_t)(brow*ROWB + bbyt);

    const char* xsrc = (const char*)g_Xq + (size_t)mt0 * (NKT*128*64);
    const char* bsrc = (const char*)g_Bpk;

    auto stage = [&](int kt, int buf){
        uint32_t ad = s2u(Abuf[buf]);
        uint32_t bd = s2u(Bbuf[buf]);
        const char* xs = xsrc + (size_t)kt*(128*64);
        const char* bs = bsrc + ((size_t)kt*512 + n0)*64;
        #pragma unroll
        for (int i = 0; i < 2; i++){
            int g = tid + i*256;
            int row = g >> 2, cb = (g & 3)*16;
            cp16(ad + row*ROWB + cb, xs + row*64 + cb);
        }
        #pragma unroll
        for (int i = 0; i < 2; i++){
            int g = tid + i*256;
            int row = g >> 2, cb = (g & 3)*16;
            cp16(bd + row*ROWB + cb, bs + row*64 + cb);
        }
    };

    unsigned int acc[2][8][2];
    #pragma unroll
    for (int mt=0; mt<2; mt++)
      #pragma unroll
      for (int nt=0; nt<8; nt++){ acc[mt][nt][0] = 0u; acc[mt][nt][1] = 0u; }

    stage(0, 0); cp_commit();
    stage(1, 1); cp_commit();

    for (int kt = 0; kt < NKT; kt++){
        int buf = kt & 3;
        if (kt + 2 < NKT){
            stage(kt + 2, (kt + 2) & 3);
            cp_commit();
            cp_wait2();
        } else {
            cp_wait0();
        }
        __syncthreads();
        const uint32_t aA = s2u(Abuf[buf]) + aoff;
        const uint32_t bA = s2u(Bbuf[buf]) + boff;
        #pragma unroll
        for (int ks = 0; ks < 2; ks++){
            unsigned int a[2][4];
            ldsm4(a[0], aA + ks*32);
            ldsm4(a[1], aA + 16*ROWB + ks*32);
            unsigned int b[8][2];
            #pragma unroll
            for (int ntp = 0; ntp < 4; ntp++){
                unsigned int r[4];
                ldsm4(r, bA + ntp*16*ROWB + ks*32);
                b[2*ntp  ][0] = r[0]; b[2*ntp  ][1] = r[1];
                b[2*ntp+1][0] = r[2]; b[2*ntp+1][1] = r[3];
            }
            #pragma unroll
            for (int nt = 0; nt < 8; nt++){
                mmaqh(acc[0][nt], a[0], b[nt][0], b[nt][1]);
                mmaqh(acc[1][nt], a[1], b[nt][0], b[nt][1]);
            }
        }
    }

    float b1r[16], w2r[16];
    #pragma unroll
    for (int nt = 0; nt < 8; nt++){
        #pragma unroll
        for (int e = 0; e < 2; e++){
            int n = n0 + warpN*64 + nt*8 + qc*2 + e;
            b1r[nt*2+e] = b1s[n];
            w2r[nt*2+e] = w2s[n];
        }
    }
    #pragma unroll
    for (int mt = 0; mt < 2; mt++){
        float sA = 0.f, sB = 0.f;
        #pragma unroll
        for (int nt = 0; nt < 8; nt++){
            float2 vA = __half22float2(*(__half2*)&acc[mt][nt][0]);
            float2 vB = __half22float2(*(__half2*)&acc[mt][nt][1]);
            sA += fmaxf(vA.x * W1INV + b1r[nt*2+0], 0.f) * w2r[nt*2+0];
            sA += fmaxf(vA.y * W1INV + b1r[nt*2+1], 0.f) * w2r[nt*2+1];
            sB += fmaxf(vB.x * W1INV + b1r[nt*2+0], 0.f) * w2r[nt*2+0];
            sB += fmaxf(vB.y * W1INV + b1r[nt*2+1], 0.f) * w2r[nt*2+1];
        }
        sA += __shfl_xor_sync(0xffffffffu, sA, 1);
        sA += __shfl_xor_sync(0xffffffffu, sA, 2);
        sB += __shfl_xor_sync(0xffffffffu, sB, 1);
        sB += __shfl_xor_sync(0xffffffffu, sB, 2);
        if (qc == 0){
            int rA = m0 + warpM*32 + mt*16 + lr;
            g_partial[(size_t)rA*8     + nc*2 + warpN] = sA;
            g_partial[(size_t)(rA+8)*8 + nc*2 + warpN] = sB;
        }
    }
}

// ============ rules: fused score (smem halo) + EOS bounds ==================
__global__ __launch_bounds__(256) void k_rule(const float* __restrict__ b2){
    __shared__ float sc[258];
    int base = blockIdx.x*256;
    int tid = threadIdx.x;
    int i = base + tid;
    float bb = __ldg(b2);
    {
        float l = bb;
        #pragma unroll
        for (int j = 0; j < 8; j++) l += g_partial[(size_t)i*8 + j];
        sc[tid + 2] = 1.f / (1.f + expf(-l));
    }
    if (tid < 2){
        int r = base - 2 + tid;
        float v = 0.f;
        if (r >= 0){
            float l = bb;
            #pragma unroll
            for (int j = 0; j < 8; j++) l += g_partial[(size_t)r*8 + j];
            v = 1.f / (1.f + expf(-l));
        }
        sc[tid] = v;
    }
    __syncthreads();
    int t = i & (SS-1);
    if (t < 2) return;
    float s0 = sc[tid+2], s1 = sc[tid+1], s2 = sc[tid];
    bool run = (s0 > 0.7f) && (s1 > 0.7f) && (s2 > 0.7f);
    float na = fmaxf(sqrtf(g_norm2[i-1]), 1e-8f);
    float nb = fmaxf(sqrtf(g_norm2[i]),   1e-8f);
    float cosv = g_dot[i-1] / (na * nb);
    bool cr = (cosv < 0.3f) && (s0 > 0.5f);
    if (run || cr){
        atomicMin(&g_first, t);
        atomicMax(&g_last,  t);
    }
}

// ================= segment pooling (early-exit prefix scan) ================
__global__ void k_pool(const float* __restrict__ X, const int* __restrict__ Mk){
    __shared__ float ssum[MAXP*DD];
    __shared__ int   scnt[MAXP];
    int b = blockIdx.x;
    int tid = threadIdx.x;
    for (int i = tid; i < MAXP*DD; i += 256) ssum[i] = 0.f;
    if (tid < MAXP) scnt[tid] = 0;
    __syncthreads();
    const float* xb = X + (size_t)b*SS*DD;
    const int*   mb = Mk + (size_t)b*SS;
    int c = 0;
    for (int s = 0; s < SS && c < MAXP; s++){
        #pragma unroll
        for (int j = 0; j < 4; j++){
            int d = tid + j*256;
            ssum[c*DD + d] += xb[(size_t)s*DD + d];
        }
        if (tid == 0) scnt[c]++;
        c += (mb[s] != 0) ? 1 : 0;
    }
    __syncthreads();
    #pragma unroll
    for (int p = 0; p < MAXP; p++){
        float inv = 1.f / (float)max(scnt[p], 1);
        #pragma unroll
        for (int j = 0; j < 4; j++){
            int d = tid + j*256;
            g_pooled[((size_t)b*MAXP + p)*DD + d] = ssum[p*DD + d] * inv;
        }
    }
}

// ======== patch split-k pass 1: partial[ks][b][p][o] over 128-k chunk ======
__global__ __launch_bounds__(128) void k_patch1(const float* __restrict__ Pw){
    __shared__ float ps[MAXP*128];    // 8 rows x 128 k = 4 KB
    int oc = blockIdx.x, b = blockIdx.y, ks = blockIdx.z;
    int tid = threadIdx.x;            // 128
    #pragma unroll
    for (int j = 0; j < 8; j++){
        int e = tid + j*128;          // 1024 elems
        int p = e >> 7, d = e & 127;
        ps[p*128 + d] = g_pooled[((size_t)b*MAXP + p)*DD + ks*128 + d];
    }
    __syncthreads();
    int o = oc*128 + tid;
    float acc[MAXP];
    #pragma unroll
    for (int p = 0; p < MAXP; p++) acc[p] = 0.f;
    const float* pw = Pw + (size_t)(ks*128)*DD + o;
    #pragma unroll 4
    for (int d = 0; d < 128; d++){
        float w = pw[(size_t)d*DD];
        #pragma unroll
        for (int p = 0; p < MAXP; p++) acc[p] += ps[p*128 + d] * w;
    }
    #pragma unroll
    for (int p = 0; p < MAXP; p++)
        g_ppart[(((size_t)ks*BB + b)*MAXP + p)*DD + o] = acc[p];
}

// ======== patch split-k pass 2: reduce 8 partials + bias -> out ============
__global__ __launch_bounds__(256) void k_patch2(const float* __restrict__ Pb,
                                                float* __restrict__ out){
    int i = blockIdx.x*256 + threadIdx.x;     // 65536 outputs
    if (i >= BB*MAXP*DD) return;
    int o = i & (DD-1);
    float s = Pb[o];
    #pragma unroll
    for (int ks = 0; ks < KSP; ks++)
        s += g_ppart[(size_t)ks*(BB*MAXP*DD) + i];
    out[i] = s;
}

// ================= finalize bounds =========================================
__global__ void k_final(float* __restrict__ out, int out_size){
    if (threadIdx.x == 0 && blockIdx.x == 0){
        int f = g_first, l = g_last;
        float s0 = -1.f, s1 = -1.f;
        if (f != 0x7fffffff){
            s0 = (float)max(0, f - 2);
            s1 = (float)min(SS - 1, l + 2);
        }
        if (out_size >= BB*MAXP*DD + 2){
            out[BB*MAXP*DD + 0] = s0;
            out[BB*MAXP*DD + 1] = s1;
        }
    }
}

// ===========================================================================
extern "C" void kernel_launch(void* const* d_in, const int* in_sizes, int n_in,
                              void* d_out, int out_size) {
    const float* latent = (const float*)d_in[0];
    const int*   mask   = (const int*)  d_in[1];
    const float* proj_w = (const float*)d_in[2];
    const float* proj_b = (const float*)d_in[3];
    const float* w1     = (const float*)d_in[4];
    const float* b1     = (const float*)d_in[5];
    const float* w2     = (const float*)d_in[6];
    const float* b2     = (const float*)d_in[7];
    float* out = (float*)d_out;

    cudaFuncSetAttribute(k_gemm, cudaFuncAttributeMaxDynamicSharedMemorySize, SM_DYN);

    // launch order keeps k_gemm as the 6th launch for ncu (-s 5 -c 1)
    k_init  <<< 1, 1 >>>();
    k_prep  <<< (NKT*FF*16 + 255)/256, 256 >>>(w1);
    k_cos   <<< M_TOTAL/32, 256 >>>(latent);
    k_pool  <<< BB, 256 >>>(latent, mask);
    k_patch1<<< dim3(DD/128, BB, KSP), 128 >>>(proj_w);
    k_gemm  <<< dim3(4, M_TOTAL/128), 256, SM_DYN >>>(b1, w2);
    k_patch2<<< (BB*MAXP*DD + 255)/256, 256 >>>(proj_b, out);
    k_rule  <<< M_TOTAL/256, 256 >>>(b2);
    k_final <<< 1, 32 >>>(out, out_size);
}